// round 13
// baseline (speedup 1.0000x reference)
#include <cuda_runtime.h>
#include <cuda_bf16.h>
#include <math.h>
#include <stdint.h>

#define NB 512
#define NS 65536
#define DD 256
#define SPLITS 32
#define KCHUNK (NS / SPLITS)   // 2048
#define NBLK 512
#define WCH 8          // sharp chunks per row

// ---------------- scratch (device globals; no allocations allowed) ----------
__device__ __nv_bfloat16 g_simb[(size_t)NB * NS];   // 64 MB : E = exp(sim), bf16
__device__ __nv_bfloat16 g_wwb [(size_t)NB * NS];   // 64 MB : sharp (pre-normalize), bf16
__device__ __nv_bfloat16 g_memb[(size_t)NS * DD];   // 32 MB : bf16 memory
__device__ __nv_bfloat16 g_qnb [NB * DD];
__device__ __nv_bfloat16 g_valb[NB * DD];
__device__ float g_qn [NB * DD];
__device__ float g_minv[NS];
__device__ float g_pmax[(size_t)NB * NBLK];
__device__ float g_psum[(size_t)NB * NBLK];
__device__ int   g_argmax[NB];
__device__ float g_cZinv[NB];
__device__ float g_ws1[NB * WCH];
__device__ float g_ws2[NB * WCH];
__device__ float g_wsinv[NB];
__device__ float g_wZinv[NB];
__device__ float g_partial[(size_t)SPLITS * NB * DD];  // 16 MB

// ======================= helpers ============================================
__device__ __forceinline__ uint32_t smem_u32(const void* p) {
    uint32_t a;
    asm("{ .reg .u64 t; cvta.to.shared.u64 t, %1; cvt.u32.u64 %0, t; }" : "=r"(a) : "l"(p));
    return a;
}
__device__ __forceinline__ uint32_t pack_bf16x2(float lo, float hi) {
    uint32_t r;
    asm("cvt.rn.bf16x2.f32 %0, %1, %2;" : "=r"(r) : "f"(hi), "f"(lo));
    return r;
}
__device__ __forceinline__ void unpack2(uint32_t u, float& a, float& b) {
    __nv_bfloat162 h = *reinterpret_cast<__nv_bfloat162*>(&u);
    a = __bfloat162float(h.x); b = __bfloat162float(h.y);
}
__device__ __forceinline__ void ldsm4(uint32_t* r, uint32_t addr) {
    asm volatile("ldmatrix.sync.aligned.m8n8.x4.shared.b16 {%0,%1,%2,%3}, [%4];"
        : "=r"(r[0]), "=r"(r[1]), "=r"(r[2]), "=r"(r[3]) : "r"(addr));
}
__device__ __forceinline__ void ldsm4t(uint32_t* r, uint32_t addr) {
    asm volatile("ldmatrix.sync.aligned.m8n8.x4.trans.shared.b16 {%0,%1,%2,%3}, [%4];"
        : "=r"(r[0]), "=r"(r[1]), "=r"(r[2]), "=r"(r[3]) : "r"(addr));
}
__device__ __forceinline__ void mma_bf16(float* c, const uint32_t* a, uint32_t b0, uint32_t b1) {
    asm volatile("mma.sync.aligned.m16n8k16.row.col.f32.bf16.bf16.f32 "
        "{%0,%1,%2,%3}, {%4,%5,%6,%7}, {%8,%9}, {%0,%1,%2,%3};"
        : "+f"(c[0]), "+f"(c[1]), "+f"(c[2]), "+f"(c[3])
        : "r"(a[0]), "r"(a[1]), "r"(a[2]), "r"(a[3]), "r"(b0), "r"(b1));
}
__device__ __forceinline__ void cp16(uint32_t d, const void* s) {
    asm volatile("cp.async.cg.shared.global [%0], [%1], 16;" :: "r"(d), "l"(s) : "memory");
}
#define CP_COMMIT() asm volatile("cp.async.commit_group;" ::: "memory")
#define CP_WAIT2()  asm volatile("cp.async.wait_group 2;" ::: "memory")

extern __shared__ __align__(16) char dsm[];

// ===== merged pre-pass: sharp (blocks 0..4095) + norms/bf16-convert =========
__global__ void __launch_bounds__(256) k_pre(const float* __restrict__ mem,
                                             const float* __restrict__ q,
                                             const float* __restrict__ val,
                                             const float* __restrict__ prev,
                                             const float* __restrict__ sw) {
    __shared__ float r1[256], r2[256];
    int bx = blockIdx.x, t = threadIdx.x;
    if (bx < NB * WCH) {
        int b = bx >> 3, ch = bx & 7, lane = t & 31;
        const float* row = prev + (size_t)b * NS;
        __nv_bfloat16* wr = g_wwb + (size_t)b * NS;
        float w0 = sw[0], w1 = sw[1], w2 = sw[2];
        int base = ch * (NS / WCH);
        float s1 = 0.f, s2 = 0.f;
        #pragma unroll
        for (int it = 0; it < NS / WCH / 1024; it++) {
            int i4 = base + (it * 256 + t) * 4;
            float4 v = *reinterpret_cast<const float4*>(row + i4);
            float pl = __shfl_up_sync(0xffffffffu, v.w, 1);
            float nx = __shfl_down_sync(0xffffffffu, v.x, 1);
            if (lane == 0)  pl = (i4 > 0) ? row[i4 - 1] : 0.f;
            if (lane == 31) nx = (i4 + 4 < NS) ? row[i4 + 4] : 0.f;
            float a0 = pl*w0 + v.x*w1 + v.y*w2;
            float a1 = v.x*w0 + v.y*w1 + v.z*w2;
            float a2 = v.y*w0 + v.z*w1 + v.w*w2;
            float a3 = v.z*w0 + v.w*w1 + nx*w2;
            float p0 = a0*a0*rsqrtf(fmaxf(a0, 1e-35f));
            float p1 = a1*a1*rsqrtf(fmaxf(a1, 1e-35f));
            float p2 = a2*a2*rsqrtf(fmaxf(a2, 1e-35f));
            float p3 = a3*a3*rsqrtf(fmaxf(a3, 1e-35f));
            s1 += p0 + p1 + p2 + p3;
            s2 += p0*p0 + p1*p1 + p2*p2 + p3*p3;
            *reinterpret_cast<uint2*>(wr + i4) =
                make_uint2(pack_bf16x2(p0, p1), pack_bf16x2(p2, p3));
        }
        r1[t] = s1; r2[t] = s2; __syncthreads();
        for (int o = 128; o; o >>= 1) {
            if (t < o) { r1[t] += r1[t+o]; r2[t] += r2[t+o]; }
            __syncthreads();
        }
        if (t == 0) { g_ws1[b * WCH + ch] = r1[0]; g_ws2[b * WCH + ch] = r2[0]; }
        return;
    }
    int lane = t & 31;
    int row = (bx - NB * WCH) * 8 + (t >> 5);
    if (row < NS) {
        const float4* p = reinterpret_cast<const float4*>(mem + (size_t)row * DD);
        float4 v0 = p[lane];
        float4 v1 = p[lane + 32];
        float s = v0.x*v0.x + v0.y*v0.y + v0.z*v0.z + v0.w*v0.w
                + v1.x*v1.x + v1.y*v1.y + v1.z*v1.z + v1.w*v1.w;
        #pragma unroll
        for (int o = 16; o; o >>= 1) s += __shfl_xor_sync(0xffffffffu, s, o);
        if (lane == 0) g_minv[row] = 1.0f / fmaxf(sqrtf(s), 1e-12f);
        __nv_bfloat16* d = g_memb + (size_t)row * DD;
        *reinterpret_cast<uint2*>(d + lane*4) =
            make_uint2(pack_bf16x2(v0.x, v0.y), pack_bf16x2(v0.z, v0.w));
        *reinterpret_cast<uint2*>(d + 128 + lane*4) =
            make_uint2(pack_bf16x2(v1.x, v1.y), pack_bf16x2(v1.z, v1.w));
    } else if (row < NS + NB) {
        int qr = row - NS;
        const float4* p = reinterpret_cast<const float4*>(q + (size_t)qr * DD);
        float4 v0 = p[lane];
        float4 v1 = p[lane + 32];
        float s = v0.x*v0.x + v0.y*v0.y + v0.z*v0.z + v0.w*v0.w
                + v1.x*v1.x + v1.y*v1.y + v1.z*v1.z + v1.w*v1.w;
        #pragma unroll
        for (int o = 16; o; o >>= 1) s += __shfl_xor_sync(0xffffffffu, s, o);
        float inv = 1.0f / fmaxf(sqrtf(s), 1e-12f);
        v0.x *= inv; v0.y *= inv; v0.z *= inv; v0.w *= inv;
        v1.x *= inv; v1.y *= inv; v1.z *= inv; v1.w *= inv;
        float4* o4 = reinterpret_cast<float4*>(g_qn + (size_t)qr * DD);
        o4[lane] = v0; o4[lane + 32] = v1;
        __nv_bfloat16* d = g_qnb + (size_t)qr * DD;
        *reinterpret_cast<uint2*>(d + lane*4) =
            make_uint2(pack_bf16x2(v0.x, v0.y), pack_bf16x2(v0.z, v0.w));
        *reinterpret_cast<uint2*>(d + 128 + lane*4) =
            make_uint2(pack_bf16x2(v1.x, v1.y), pack_bf16x2(v1.z, v1.w));
    } else {
        int vr = row - NS - NB;
        const float4* p = reinterpret_cast<const float4*>(val + (size_t)vr * DD);
        float4 v0 = p[lane];
        float4 v1 = p[lane + 32];
        __nv_bfloat16* d = g_valb + (size_t)vr * DD;
        *reinterpret_cast<uint2*>(d + lane*4) =
            make_uint2(pack_bf16x2(v0.x, v0.y), pack_bf16x2(v0.z, v0.w));
        *reinterpret_cast<uint2*>(d + 128 + lane*4) =
            make_uint2(pack_bf16x2(v1.x, v1.y), pack_bf16x2(v1.z, v1.w));
    }
}

// ============ sim GEMM (HMMA bf16, cp.async 4-stage) + exp epilogue =========
// dsm: A stages s*10240 (4), B stages 40960+s*10240 (4), minv @ 81920
#define SIM_DSM 82432
__global__ void __launch_bounds__(256, 2) k_sim() {
    float* s_minv = reinterpret_cast<float*>(dsm + 81920);
    int tid = threadIdx.x, lane = tid & 31, w = tid >> 5;
    int wm = w >> 2, wn = w & 3;
    int bn = blockIdx.x * 128, bm = blockIdx.y * 128;
    uint32_t sb = smem_u32(dsm);
    if (tid < 32) reinterpret_cast<float4*>(s_minv)[tid] =
        reinterpret_cast<const float4*>(g_minv + bn)[tid];

    float acc[4][4][4];
    #pragma unroll
    for (int i = 0; i < 4; i++)
        #pragma unroll
        for (int j = 0; j < 4; j++)
            #pragma unroll
            for (int u = 0; u < 4; u++) acc[i][j][u] = 0.f;

    int r = lane & 7, gq = lane >> 3;

    auto issue = [&](int it) {
        if (it < 8) {
            int k0 = it * 32;
            uint32_t sa = sb + (it & 3) * 10240;
            uint32_t sbb = sb + 40960 + (it & 3) * 10240;
            #pragma unroll
            for (int i = 0; i < 2; i++) {
                int idx = tid + i * 256;
                int row = idx >> 2, q8 = (idx & 3) * 8;
                cp16(sa  + (uint32_t)(row*80 + q8*2), g_qnb  + (size_t)(bm + row) * DD + k0 + q8);
                cp16(sbb + (uint32_t)(row*80 + q8*2), g_memb + (size_t)(bn + row) * DD + k0 + q8);
            }
        }
        CP_COMMIT();
    };
    issue(0); issue(1); issue(2);

    for (int ch = 0; ch < 8; ch++) {
        CP_WAIT2();
        __syncthreads();
        issue(ch + 3);
        uint32_t aA = sb + (ch & 3) * 10240;
        uint32_t aB = sb + 40960 + (ch & 3) * 10240;
        #pragma unroll
        for (int ks = 0; ks < 2; ks++) {
            int kk = ks * 16;
            uint32_t ah[4][4], bh[2][4];
            #pragma unroll
            for (int mt = 0; mt < 4; mt++) {
                int arow = wm*64 + mt*16 + r + 8*(gq & 1);
                int acol = kk + 8*(gq >> 1);
                ldsm4(ah[mt], aA + (uint32_t)(arow*80 + acol*2));
            }
            #pragma unroll
            for (int np = 0; np < 2; np++) {
                int brow = wn*32 + np*16 + r + 8*(gq >> 1);
                int bcol = kk + 8*(gq & 1);
                ldsm4(bh[np], aB + (uint32_t)(brow*80 + bcol*2));
            }
            #pragma unroll
            for (int mt = 0; mt < 4; mt++)
                #pragma unroll
                for (int nt = 0; nt < 4; nt++) {
                    int np = nt >> 1, hb = (nt & 1) * 2;
                    mma_bf16(acc[mt][nt], ah[mt], bh[np][hb], bh[np][hb+1]);
                }
        }
    }
    __syncthreads();

    float* s_max = reinterpret_cast<float*>(dsm);
    float* s_sum = reinterpret_cast<float*>(dsm + 40960);
    int g = lane >> 2, t = lane & 3;
    #pragma unroll
    for (int mt = 0; mt < 4; mt++)
        #pragma unroll
        for (int rs = 0; rs < 2; rs++) {
            int mloc = wm*64 + mt*16 + g + rs*8;
            float lm = -1e30f; float ls = 0.f;
            #pragma unroll
            for (int nt = 0; nt < 4; nt++) {
                int ncl = wn*32 + nt*8 + t*2;
                float s0 = acc[mt][nt][rs*2]   * s_minv[ncl];
                float s1 = acc[mt][nt][rs*2+1] * s_minv[ncl+1];
                lm = fmaxf(lm, fmaxf(s0, s1));
                float e0 = __expf(s0), e1 = __expf(s1);
                ls += e0 + e1;
                *reinterpret_cast<uint32_t*>(g_simb + (size_t)(bm + mloc) * NS + bn + ncl) =
                    pack_bf16x2(e0, e1);
            }
            #pragma unroll
            for (int o = 1; o < 4; o <<= 1) {
                lm = fmaxf(lm, __shfl_xor_sync(0xffffffffu, lm, o));
                ls += __shfl_xor_sync(0xffffffffu, ls, o);
            }
            if (t == 0) {
                s_max[wn*128 + mloc] = lm;
                s_sum[wn*128 + mloc] = ls;
            }
        }
    __syncthreads();
    if (tid < 128) {
        float m = s_max[tid]; float s = s_sum[tid];
        #pragma unroll
        for (int wq = 1; wq < 4; wq++) {
            m = fmaxf(m, s_max[wq*128 + tid]);
            s += s_sum[wq*128 + tid];
        }
        size_t pidx = (size_t)(bm + tid) * NBLK + blockIdx.x;
        g_pmax[pidx] = m; g_psum[pidx] = s;
    }
}

// ------- combine: Z + two-stage argmax (block -> slot via E) + wcomb + topk --
__global__ void __launch_bounds__(256) k_combine(const float* __restrict__ mem,
                                                 float* __restrict__ out2) {
    int b = blockIdx.x, t = threadIdx.x, lane = t & 31, w = t >> 5;
    size_t base = (size_t)b * NBLK;
    float p1 = g_pmax[base + t], p2 = g_pmax[base + t + 256];
    float m = fmaxf(p1, p2);
    float s = g_psum[base + t] + g_psum[base + t + 256];
    __shared__ float sm[256]; __shared__ float ss[256];
    __shared__ float s_q[DD];
    __shared__ int s_cnt, s_cand[64];
    __shared__ int s_scnt, s_slot[64];
    __shared__ float s_bv[8]; __shared__ int s_bi[8];
    __shared__ int s_arg;
    if (t == 0) { s_cnt = 0; s_scnt = 0; }
    if (t < 64) reinterpret_cast<float4*>(s_q)[t] =
        reinterpret_cast<const float4*>(g_qn + (size_t)b * DD)[t];
    sm[t] = m; ss[t] = s; __syncthreads();
    for (int o = 128; o; o >>= 1) {
        if (t < o) { ss[t] += ss[t+o]; sm[t] = fmaxf(sm[t], sm[t+o]); }
        __syncthreads();
    }
    float rm = sm[0];
    if (t == 0) {
        g_cZinv[b] = 1.0f / ss[0];
        float s1 = 0.f, s2 = 0.f;
        #pragma unroll
        for (int c = 0; c < WCH; c++) { s1 += g_ws1[b*WCH + c]; s2 += g_ws2[b*WCH + c]; }
        float sinv = 1.0f / (s1 + 1e-8f);
        float z = (float)NS + s1 * sinv + 0.5f * s2 * sinv * sinv;
        g_wsinv[b] = sinv;
        g_wZinv[b] = 1.0f / z;
    }
    float thr = rm - 8e-3f;
    if (p1 >= thr) { int p = atomicAdd(&s_cnt, 1); if (p < 64) s_cand[p] = t; }
    if (p2 >= thr) { int p = atomicAdd(&s_cnt, 1); if (p < 64) s_cand[p] = t + 256; }
    __syncthreads();
    int nc = min(s_cnt, 64);
    float Eth = __expf(rm - 8e-3f) * 0.992f;
    const __nv_bfloat16* Erow = g_simb + (size_t)b * NS;
    for (int i = t; i < nc * 128; i += 256) {
        int n = s_cand[i >> 7] * 128 + (i & 127);
        if (__bfloat162float(Erow[n]) >= Eth) {
            int p = atomicAdd(&s_scnt, 1);
            if (p < 64) s_slot[p] = n;
        }
    }
    __syncthreads();
    int nsl = min(s_scnt, 64);
    float bv = -1e30f; int bi = 0x7fffffff;
    for (int c = w; c < nsl; c += 8) {
        int n = s_slot[c];
        const float* mr = mem + (size_t)n * DD;
        float d = 0.f;
        #pragma unroll
        for (int j = 0; j < 8; j += 4) {
            float4 qv = *reinterpret_cast<const float4*>(s_q + lane*8 + j);
            float4 mv = *reinterpret_cast<const float4*>(mr + lane*8 + j);
            d += qv.x*mv.x + qv.y*mv.y + qv.z*mv.z + qv.w*mv.w;
        }
        #pragma unroll
        for (int o = 16; o; o >>= 1) d += __shfl_xor_sync(0xffffffffu, d, o);
        d *= g_minv[n];
        if (lane == 0) {
            if (d > bv || (d == bv && n < bi)) { bv = d; bi = n; }
        }
    }
    if (lane == 0) { s_bv[w] = bv; s_bi[w] = bi; }
    __syncthreads();
    if (t == 0) {
        float v = s_bv[0]; int ix = s_bi[0];
        #pragma unroll
        for (int k = 1; k < 8; k++)
            if (s_bv[k] > v || (s_bv[k] == v && s_bi[k] < ix)) { v = s_bv[k]; ix = s_bi[k]; }
        g_argmax[b] = ix;
        s_arg = ix;
    }
    __syncthreads();
    out2[(size_t)b * DD + t] = mem[(size_t)s_arg * DD + t];
}

// ======= merged GEMM kernel, 256 threads, 128x64 tiles, 3 CTA/SM ============
// content blocks [0, 512): z=bx>>4, bm=((bx>>2)&3)*128, bd=(bx&3)*64
// newmem blocks [512, 2560): bm=(bx>>2)*128, bd=(bx&3)*64
// content smem: A 4 stages @ s*10240 (40960), B 4 stages @ 40960+s*4608 (18432)
// newmem smem:  A 2 @ s*8704 (17408), B 2 @ 17408+s*4608, red@26624, sinv@34816,
//               zinv@36864, erase@38912
#define CNM_DSM 59392
#define CONT_BLKS 512

__device__ __forceinline__ void content_body(int bx) {
    int tid = threadIdx.x, lane = tid & 31, w = tid >> 5;
    int wm = w >> 1, wn = w & 1;
    int z = bx >> 4, bm = ((bx >> 2) & 3) * 128, bd = (bx & 3) * 64;
    uint32_t sb = smem_u32(dsm);
    float acc[2][4][4];
    #pragma unroll
    for (int i = 0; i < 2; i++)
        #pragma unroll
        for (int j = 0; j < 4; j++)
            #pragma unroll
            for (int u = 0; u < 4; u++) acc[i][j][u] = 0.f;
    int r = lane & 7, gq = lane >> 3;
    int kbase = z * KCHUNK;
    const int NIT = KCHUNK / 32;   // 64

    auto issue = [&](int it) {
        if (it < NIT) {
            int k0 = kbase + it * 32;
            uint32_t sa = sb + (it & 3) * 10240;
            uint32_t sbb = sb + 40960 + (it & 3) * 4608;
            #pragma unroll
            for (int i = 0; i < 2; i++) {
                int idx = tid + i * 256;
                int ar = idx >> 2, aq8 = (idx & 3) * 8;
                cp16(sa + (uint32_t)(ar*80 + aq8*2),
                     g_simb + (size_t)(bm + ar) * NS + k0 + aq8);
            }
            int br = tid >> 3, bq8 = (tid & 7) * 8;
            cp16(sbb + (uint32_t)(br*144 + bq8*2),
                 g_memb + (size_t)(k0 + br) * DD + bd + bq8);
        }
        CP_COMMIT();
    };
    issue(0); issue(1); issue(2);

    for (int it = 0; it < NIT; it++) {
        CP_WAIT2();
        __syncthreads();
        issue(it + 3);
        uint32_t aA = sb + (it & 3) * 10240;
        uint32_t aB = sb + 40960 + (it & 3) * 4608;
        #pragma unroll
        for (int ks = 0; ks < 2; ks++) {
            int kk = ks * 16;
            uint32_t af[2][4], bf[2][4];
            #pragma unroll
            for (int mt = 0; mt < 2; mt++) {
                int arow = wm*32 + mt*16 + r + 8*(gq & 1);
                int acol = kk + 8*(gq >> 1);
                ldsm4(af[mt], aA + (uint32_t)(arow*80 + acol*2));
            }
            #pragma unroll
            for (int np = 0; np < 2; np++) {
                int brow = kk + r + 8*(gq & 1);
                int bcol = wn*32 + np*16 + 8*(gq >> 1);
                ldsm4t(bf[np], aB + (uint32_t)(brow*144 + bcol*2));
            }
            #pragma unroll
            for (int mt = 0; mt < 2; mt++)
                #pragma unroll
                for (int nt = 0; nt < 4; nt++) {
                    int np = nt >> 1, hb = (nt & 1) * 2;
                    mma_bf16(acc[mt][nt], af[mt], bf[np][hb], bf[np][hb+1]);
                }
        }
    }
    int g = lane >> 2, tq = lane & 3;
    #pragma unroll
    for (int mt = 0; mt < 2; mt++)
        #pragma unroll
        for (int rs = 0; rs < 2; rs++) {
            int mloc = wm*32 + mt*16 + g + rs*8;
            float* dst = g_partial + ((size_t)z * NB + bm + mloc) * DD + bd;
            #pragma unroll
            for (int nt = 0; nt < 4; nt++) {
                int off = wn*32 + nt*8 + tq*2;
                *reinterpret_cast<float2*>(dst + off) =
                    make_float2(acc[mt][nt][rs*2], acc[mt][nt][rs*2+1]);
            }
        }
}

__device__ __forceinline__ void newmem_body(int bx, const float* __restrict__ mem,
                                            float* __restrict__ out3) {
    char* pA[2] = { dsm, dsm + 8704 };            // 32 x 128 bf16 (w), stride 272
    char* pB[2] = { dsm + 17408, dsm + 22016 };   // 32 x 64 bf16 (valb), stride 144
    float* s_red   = reinterpret_cast<float*>(dsm + 26624);   // [16][128]
    float* s_sinv  = reinterpret_cast<float*>(dsm + 34816);
    float* s_zinv  = reinterpret_cast<float*>(dsm + 36864);
    float* s_erase = reinterpret_cast<float*>(dsm + 38912);
    int tid = threadIdx.x, lane = tid & 31, w = tid >> 5;
    int wm = w >> 1, wn = w & 1;
    int bm = (bx >> 2) * 128, bd = (bx & 3) * 64;
    if (tid < 128) {
        reinterpret_cast<float4*>(s_sinv)[tid] = reinterpret_cast<const float4*>(g_wsinv)[tid];
        reinterpret_cast<float4*>(s_zinv)[tid] = reinterpret_cast<const float4*>(g_wZinv)[tid];
    }
    float acc[2][4][4];
    #pragma unroll
    for (int i = 0; i < 2; i++)
        #pragma unroll
        for (int j = 0; j < 4; j++)
            #pragma unroll
            for (int u = 0; u < 4; u++) acc[i][j][u] = 0.f;
    float pr[8];
    #pragma unroll
    for (int j = 0; j < 8; j++) pr[j] = 1.f;
    int r = lane & 7, gq = lane >> 3;
    int ac8 = (tid & 15) * 8;
    int vbr = tid >> 3, vq8 = (tid & 7) * 8;
    __syncthreads();

    auto storeA = [&](int st, int rowoff, int krow, uint4 u) {
        float sv = s_sinv[krow], zv = s_zinv[krow];
        float f[8];
        unpack2(u.x, f[0], f[1]); unpack2(u.y, f[2], f[3]);
        unpack2(u.z, f[4], f[5]); unpack2(u.w, f[6], f[7]);
        uint32_t stv[4];
        #pragma unroll
        for (int j = 0; j < 8; j += 2) {
            float x0 = f[j] * sv, x1 = f[j+1] * sv;
            float w0 = (1.f + x0 + 0.5f*x0*x0) * zv;
            float w1 = (1.f + x1 + 0.5f*x1*x1) * zv;
            pr[j]   *= (1.f - 0.5f*w0);
            pr[j+1] *= (1.f - 0.5f*w1);
            stv[j >> 1] = pack_bf16x2(w0, w1);
        }
        *reinterpret_cast<uint4*>(pA[st] + rowoff*272 + ac8*2) =
            make_uint4(stv[0], stv[1], stv[2], stv[3]);
    };

    {
        #pragma unroll
        for (int i = 0; i < 2; i++) {
            int idx = tid + i * 256;
            int ar = idx >> 4;
            uint4 u = *reinterpret_cast<const uint4*>(g_wwb + (size_t)ar * NS + bm + ac8);
            storeA(0, ar, ar, u);
        }
        *reinterpret_cast<uint4*>(pB[0] + vbr*144 + vq8*2) =
            *reinterpret_cast<const uint4*>(g_valb + (size_t)vbr * DD + bd + vq8);
    }
    __syncthreads();

    uint4 pfa[2], pfb;
    for (int ch = 0; ch < 16; ch++) {
        int st = ch & 1;
        if (ch < 15) {
            int k0 = (ch + 1) * 32;
            #pragma unroll
            for (int i = 0; i < 2; i++) {
                int idx = tid + i * 256;
                int ar = idx >> 4;
                pfa[i] = *reinterpret_cast<const uint4*>(g_wwb + (size_t)(k0 + ar) * NS + bm + ac8);
            }
            pfb = *reinterpret_cast<const uint4*>(g_valb + (size_t)(k0 + vbr) * DD + bd + vq8);
        }
        uint32_t aA = smem_u32(pA[st]), aB = smem_u32(pB[st]);
        #pragma unroll
        for (int ks = 0; ks < 2; ks++) {
            int kk = ks * 16;
            uint32_t af[2][4], bf[2][4];
            #pragma unroll
            for (int mt = 0; mt < 2; mt++) {
                int arow = kk + r + 8*(gq >> 1);
                int acol = wm*32 + mt*16 + 8*(gq & 1);
                ldsm4t(af[mt], aA + (uint32_t)(arow*272 + acol*2));
            }
            #pragma unroll
            for (int np = 0; np < 2; np++) {
                int brow = kk + r + 8*(gq & 1);
                int bcol = wn*32 + np*16 + 8*(gq >> 1);
                ldsm4t(bf[np], aB + (uint32_t)(brow*144 + bcol*2));
            }
            #pragma unroll
            for (int mt = 0; mt < 2; mt++)
                #pragma unroll
                for (int nt = 0; nt < 4; nt++) {
                    int np = nt >> 1, hb = (nt & 1) * 2;
                    mma_bf16(acc[mt][nt], af[mt], bf[np][hb], bf[np][hb+1]);
                }
        }
        if (ch < 15) {
            int ns = st ^ 1;
            int k0 = (ch + 1) * 32;
            #pragma unroll
            for (int i = 0; i < 2; i++) {
                int idx = tid + i * 256;
                int ar = idx >> 4;
                storeA(ns, ar, k0 + ar, pfa[i]);
            }
            *reinterpret_cast<uint4*>(pB[ns] + vbr*144 + vq8*2) = pfb;
            __syncthreads();
        }
    }
    __syncthreads();
    #pragma unroll
    for (int j = 0; j < 8; j++) s_red[(tid >> 4)*128 + ac8 + j] = pr[j];
    __syncthreads();
    if (tid < 128) {
        float p = 1.f;
        #pragma unroll
        for (int k = 0; k < 16; k++) p *= s_red[k*128 + tid];
        s_erase[tid] = p;
    }
    __syncthreads();
    int g = lane >> 2, tq = lane & 3;
    #pragma unroll
    for (int mt = 0; mt < 2; mt++)
        #pragma unroll
        for (int rs = 0; rs < 2; rs++) {
            int mloc = wm*32 + mt*16 + g + rs*8;
            int slot = bm + mloc;
            float er = s_erase[mloc];
            const float* mrow = mem + (size_t)slot * DD + bd;
            float* dst = out3 + (size_t)slot * DD + bd;
            #pragma unroll
            for (int nt = 0; nt < 4; nt++) {
                int off = wn*32 + nt*8 + tq*2;
                float2 mv = *reinterpret_cast<const float2*>(mrow + off);
                *reinterpret_cast<float2*>(dst + off) =
                    make_float2(mv.x*er + acc[mt][nt][rs*2], mv.y*er + acc[mt][nt][rs*2+1]);
            }
        }
}

__global__ void __launch_bounds__(256, 3) k_cnm(const float* __restrict__ mem,
                                                float* __restrict__ out3) {
    if (blockIdx.x < CONT_BLKS) content_body(blockIdx.x);
    else                        newmem_body(blockIdx.x - CONT_BLKS, mem, out3);
}

// ---------------- reduce split-K partials, scale by 1/Z ----------------------
__global__ void __launch_bounds__(256) k_reduce(float* __restrict__ out1) {
    int idx = blockIdx.x * 256 + threadIdx.x;
    int b = idx >> 8;
    float s = 0.f;
    #pragma unroll
    for (int z = 0; z < SPLITS; z++) s += g_partial[(size_t)z * NB * DD + idx];
    out1[idx] = s * g_cZinv[b];
}

// ---------------- launch ----------------------------------------------------
extern "C" void kernel_launch(void* const* d_in, const int* in_sizes, int n_in,
                              void* d_out, int out_size) {
    const float* memory  = (const float*)d_in[0];
    const float* query   = (const float*)d_in[1];
    const float* value   = (const float*)d_in[2];
    const float* prev    = (const float*)d_in[3];
    const float* shiftw  = (const float*)d_in[4];

    float* out  = (float*)d_out;
    float* out1 = out;                     // read_content [512,256]
    float* out2 = out + NB * DD;           // read_topk    [512,256]
    float* out3 = out + 2 * NB * DD;       // new_mem      [65536,256]

    cudaFuncSetAttribute(k_sim, cudaFuncAttributeMaxDynamicSharedMemorySize, SIM_DSM);
    cudaFuncSetAttribute(k_cnm, cudaFuncAttributeMaxDynamicSharedMemorySize, CNM_DSM);

    k_pre    <<<NB * WCH + (NS + 2*NB) / 8, 256>>>(memory, query, value, prev, shiftw);
    k_sim    <<<dim3(NS / 128, NB / 128), 256, SIM_DSM>>>();
    k_combine<<<NB, 256>>>(memory, out2);
    k_cnm    <<<CONT_BLKS + 4 * (NS / 128), 256, CNM_DSM>>>(memory, out3);
    k_reduce <<<(NB * DD) / 256, 256>>>(out1);
}

// round 14
// speedup vs baseline: 1.1491x; 1.1491x over previous
#include <cuda_runtime.h>
#include <cuda_bf16.h>
#include <math.h>
#include <stdint.h>

#define NB 512
#define NS 65536
#define DD 256
#define SPLITS 32
#define KCHUNK (NS / SPLITS)   // 2048
#define NBLK 512
#define WCH 8          // sharp chunks per row

// ---------------- scratch (device globals; no allocations allowed) ----------
__device__ __nv_bfloat16 g_simb[(size_t)NB * NS];   // 64 MB : E = exp(sim), bf16
__device__ __nv_bfloat16 g_wwb [(size_t)NB * NS];   // 64 MB : sharp (pre-normalize), bf16
__device__ __nv_bfloat16 g_memb[(size_t)NS * DD];   // 32 MB : bf16 memory
__device__ __nv_bfloat16 g_qnb [NB * DD];
__device__ __nv_bfloat16 g_valb[NB * DD];
__device__ float g_qn [NB * DD];
__device__ float g_minv[NS];
__device__ float g_pmax[(size_t)NB * NBLK];
__device__ float g_psum[(size_t)NB * NBLK];
__device__ int   g_argmax[NB];
__device__ float g_cZinv[NB];
__device__ float g_ws1[NB * WCH];
__device__ float g_ws2[NB * WCH];
__device__ float g_wsinv[NB];
__device__ float g_wZinv[NB];
__device__ float g_partial[(size_t)SPLITS * NB * DD];  // 16 MB

// ======================= helpers ============================================
__device__ __forceinline__ uint32_t smem_u32(const void* p) {
    uint32_t a;
    asm("{ .reg .u64 t; cvta.to.shared.u64 t, %1; cvt.u32.u64 %0, t; }" : "=r"(a) : "l"(p));
    return a;
}
__device__ __forceinline__ uint32_t pack_bf16x2(float lo, float hi) {
    uint32_t r;
    asm("cvt.rn.bf16x2.f32 %0, %1, %2;" : "=r"(r) : "f"(hi), "f"(lo));
    return r;
}
__device__ __forceinline__ void unpack2(uint32_t u, float& a, float& b) {
    __nv_bfloat162 h = *reinterpret_cast<__nv_bfloat162*>(&u);
    a = __bfloat162float(h.x); b = __bfloat162float(h.y);
}
__device__ __forceinline__ void ldsm4(uint32_t* r, uint32_t addr) {
    asm volatile("ldmatrix.sync.aligned.m8n8.x4.shared.b16 {%0,%1,%2,%3}, [%4];"
        : "=r"(r[0]), "=r"(r[1]), "=r"(r[2]), "=r"(r[3]) : "r"(addr));
}
__device__ __forceinline__ void ldsm4t(uint32_t* r, uint32_t addr) {
    asm volatile("ldmatrix.sync.aligned.m8n8.x4.trans.shared.b16 {%0,%1,%2,%3}, [%4];"
        : "=r"(r[0]), "=r"(r[1]), "=r"(r[2]), "=r"(r[3]) : "r"(addr));
}
__device__ __forceinline__ void mma_bf16(float* c, const uint32_t* a, uint32_t b0, uint32_t b1) {
    asm volatile("mma.sync.aligned.m16n8k16.row.col.f32.bf16.bf16.f32 "
        "{%0,%1,%2,%3}, {%4,%5,%6,%7}, {%8,%9}, {%0,%1,%2,%3};"
        : "+f"(c[0]), "+f"(c[1]), "+f"(c[2]), "+f"(c[3])
        : "r"(a[0]), "r"(a[1]), "r"(a[2]), "r"(a[3]), "r"(b0), "r"(b1));
}
__device__ __forceinline__ void cp16(uint32_t d, const void* s) {
    asm volatile("cp.async.cg.shared.global [%0], [%1], 16;" :: "r"(d), "l"(s) : "memory");
}
#define CP_COMMIT() asm volatile("cp.async.commit_group;" ::: "memory")
#define CP_WAIT2()  asm volatile("cp.async.wait_group 2;" ::: "memory")
#define CP_WAIT4()  asm volatile("cp.async.wait_group 4;" ::: "memory")

extern __shared__ __align__(16) char dsm[];

// ===== merged pre-pass: sharp (blocks 0..4095) + norms/bf16-convert =========
__global__ void __launch_bounds__(256) k_pre(const float* __restrict__ mem,
                                             const float* __restrict__ q,
                                             const float* __restrict__ val,
                                             const float* __restrict__ prev,
                                             const float* __restrict__ sw) {
    __shared__ float r1[256], r2[256];
    int bx = blockIdx.x, t = threadIdx.x;
    if (bx < NB * WCH) {
        int b = bx >> 3, ch = bx & 7, lane = t & 31;
        const float* row = prev + (size_t)b * NS;
        __nv_bfloat16* wr = g_wwb + (size_t)b * NS;
        float w0 = sw[0], w1 = sw[1], w2 = sw[2];
        int base = ch * (NS / WCH);
        float s1 = 0.f, s2 = 0.f;
        #pragma unroll
        for (int it = 0; it < NS / WCH / 1024; it++) {
            int i4 = base + (it * 256 + t) * 4;
            float4 v = *reinterpret_cast<const float4*>(row + i4);
            float pl = __shfl_up_sync(0xffffffffu, v.w, 1);
            float nx = __shfl_down_sync(0xffffffffu, v.x, 1);
            if (lane == 0)  pl = (i4 > 0) ? row[i4 - 1] : 0.f;
            if (lane == 31) nx = (i4 + 4 < NS) ? row[i4 + 4] : 0.f;
            float a0 = pl*w0 + v.x*w1 + v.y*w2;
            float a1 = v.x*w0 + v.y*w1 + v.z*w2;
            float a2 = v.y*w0 + v.z*w1 + v.w*w2;
            float a3 = v.z*w0 + v.w*w1 + nx*w2;
            float p0 = a0*a0*rsqrtf(fmaxf(a0, 1e-35f));
            float p1 = a1*a1*rsqrtf(fmaxf(a1, 1e-35f));
            float p2 = a2*a2*rsqrtf(fmaxf(a2, 1e-35f));
            float p3 = a3*a3*rsqrtf(fmaxf(a3, 1e-35f));
            s1 += p0 + p1 + p2 + p3;
            s2 += p0*p0 + p1*p1 + p2*p2 + p3*p3;
            *reinterpret_cast<uint2*>(wr + i4) =
                make_uint2(pack_bf16x2(p0, p1), pack_bf16x2(p2, p3));
        }
        r1[t] = s1; r2[t] = s2; __syncthreads();
        for (int o = 128; o; o >>= 1) {
            if (t < o) { r1[t] += r1[t+o]; r2[t] += r2[t+o]; }
            __syncthreads();
        }
        if (t == 0) { g_ws1[b * WCH + ch] = r1[0]; g_ws2[b * WCH + ch] = r2[0]; }
        return;
    }
    int lane = t & 31;
    int row = (bx - NB * WCH) * 8 + (t >> 5);
    if (row < NS) {
        const float4* p = reinterpret_cast<const float4*>(mem + (size_t)row * DD);
        float4 v0 = p[lane];
        float4 v1 = p[lane + 32];
        float s = v0.x*v0.x + v0.y*v0.y + v0.z*v0.z + v0.w*v0.w
                + v1.x*v1.x + v1.y*v1.y + v1.z*v1.z + v1.w*v1.w;
        #pragma unroll
        for (int o = 16; o; o >>= 1) s += __shfl_xor_sync(0xffffffffu, s, o);
        if (lane == 0) g_minv[row] = 1.0f / fmaxf(sqrtf(s), 1e-12f);
        __nv_bfloat16* d = g_memb + (size_t)row * DD;
        *reinterpret_cast<uint2*>(d + lane*4) =
            make_uint2(pack_bf16x2(v0.x, v0.y), pack_bf16x2(v0.z, v0.w));
        *reinterpret_cast<uint2*>(d + 128 + lane*4) =
            make_uint2(pack_bf16x2(v1.x, v1.y), pack_bf16x2(v1.z, v1.w));
    } else if (row < NS + NB) {
        int qr = row - NS;
        const float4* p = reinterpret_cast<const float4*>(q + (size_t)qr * DD);
        float4 v0 = p[lane];
        float4 v1 = p[lane + 32];
        float s = v0.x*v0.x + v0.y*v0.y + v0.z*v0.z + v0.w*v0.w
                + v1.x*v1.x + v1.y*v1.y + v1.z*v1.z + v1.w*v1.w;
        #pragma unroll
        for (int o = 16; o; o >>= 1) s += __shfl_xor_sync(0xffffffffu, s, o);
        float inv = 1.0f / fmaxf(sqrtf(s), 1e-12f);
        v0.x *= inv; v0.y *= inv; v0.z *= inv; v0.w *= inv;
        v1.x *= inv; v1.y *= inv; v1.z *= inv; v1.w *= inv;
        float4* o4 = reinterpret_cast<float4*>(g_qn + (size_t)qr * DD);
        o4[lane] = v0; o4[lane + 32] = v1;
        __nv_bfloat16* d = g_qnb + (size_t)qr * DD;
        *reinterpret_cast<uint2*>(d + lane*4) =
            make_uint2(pack_bf16x2(v0.x, v0.y), pack_bf16x2(v0.z, v0.w));
        *reinterpret_cast<uint2*>(d + 128 + lane*4) =
            make_uint2(pack_bf16x2(v1.x, v1.y), pack_bf16x2(v1.z, v1.w));
    } else {
        int vr = row - NS - NB;
        const float4* p = reinterpret_cast<const float4*>(val + (size_t)vr * DD);
        float4 v0 = p[lane];
        float4 v1 = p[lane + 32];
        __nv_bfloat16* d = g_valb + (size_t)vr * DD;
        *reinterpret_cast<uint2*>(d + lane*4) =
            make_uint2(pack_bf16x2(v0.x, v0.y), pack_bf16x2(v0.z, v0.w));
        *reinterpret_cast<uint2*>(d + 128 + lane*4) =
            make_uint2(pack_bf16x2(v1.x, v1.y), pack_bf16x2(v1.z, v1.w));
    }
}

// ============ sim GEMM (HMMA bf16, cp.async 4-stage) + exp epilogue =========
// dsm: A stages s*10240 (4), B stages 40960+s*10240 (4), minv @ 81920
#define SIM_DSM 82432
__global__ void __launch_bounds__(256, 2) k_sim() {
    float* s_minv = reinterpret_cast<float*>(dsm + 81920);
    int tid = threadIdx.x, lane = tid & 31, w = tid >> 5;
    int wm = w >> 2, wn = w & 3;
    int bn = blockIdx.x * 128, bm = blockIdx.y * 128;
    uint32_t sb = smem_u32(dsm);
    if (tid < 32) reinterpret_cast<float4*>(s_minv)[tid] =
        reinterpret_cast<const float4*>(g_minv + bn)[tid];

    float acc[4][4][4];
    #pragma unroll
    for (int i = 0; i < 4; i++)
        #pragma unroll
        for (int j = 0; j < 4; j++)
            #pragma unroll
            for (int u = 0; u < 4; u++) acc[i][j][u] = 0.f;

    int r = lane & 7, gq = lane >> 3;

    auto issue = [&](int it) {
        if (it < 8) {
            int k0 = it * 32;
            uint32_t sa = sb + (it & 3) * 10240;
            uint32_t sbb = sb + 40960 + (it & 3) * 10240;
            #pragma unroll
            for (int i = 0; i < 2; i++) {
                int idx = tid + i * 256;
                int row = idx >> 2, q8 = (idx & 3) * 8;
                cp16(sa  + (uint32_t)(row*80 + q8*2), g_qnb  + (size_t)(bm + row) * DD + k0 + q8);
                cp16(sbb + (uint32_t)(row*80 + q8*2), g_memb + (size_t)(bn + row) * DD + k0 + q8);
            }
        }
        CP_COMMIT();
    };
    issue(0); issue(1); issue(2);

    for (int ch = 0; ch < 8; ch++) {
        CP_WAIT2();
        __syncthreads();
        issue(ch + 3);
        uint32_t aA = sb + (ch & 3) * 10240;
        uint32_t aB = sb + 40960 + (ch & 3) * 10240;
        #pragma unroll
        for (int ks = 0; ks < 2; ks++) {
            int kk = ks * 16;
            uint32_t ah[4][4], bh[2][4];
            #pragma unroll
            for (int mt = 0; mt < 4; mt++) {
                int arow = wm*64 + mt*16 + r + 8*(gq & 1);
                int acol = kk + 8*(gq >> 1);
                ldsm4(ah[mt], aA + (uint32_t)(arow*80 + acol*2));
            }
            #pragma unroll
            for (int np = 0; np < 2; np++) {
                int brow = wn*32 + np*16 + r + 8*(gq >> 1);
                int bcol = kk + 8*(gq & 1);
                ldsm4(bh[np], aB + (uint32_t)(brow*80 + bcol*2));
            }
            #pragma unroll
            for (int mt = 0; mt < 4; mt++)
                #pragma unroll
                for (int nt = 0; nt < 4; nt++) {
                    int np = nt >> 1, hb = (nt & 1) * 2;
                    mma_bf16(acc[mt][nt], ah[mt], bh[np][hb], bh[np][hb+1]);
                }
        }
    }
    __syncthreads();

    float* s_max = reinterpret_cast<float*>(dsm);
    float* s_sum = reinterpret_cast<float*>(dsm + 40960);
    int g = lane >> 2, t = lane & 3;
    #pragma unroll
    for (int mt = 0; mt < 4; mt++)
        #pragma unroll
        for (int rs = 0; rs < 2; rs++) {
            int mloc = wm*64 + mt*16 + g + rs*8;
            float lm = -1e30f; float ls = 0.f;
            #pragma unroll
            for (int nt = 0; nt < 4; nt++) {
                int ncl = wn*32 + nt*8 + t*2;
                float s0 = acc[mt][nt][rs*2]   * s_minv[ncl];
                float s1 = acc[mt][nt][rs*2+1] * s_minv[ncl+1];
                lm = fmaxf(lm, fmaxf(s0, s1));
                float e0 = __expf(s0), e1 = __expf(s1);
                ls += e0 + e1;
                *reinterpret_cast<uint32_t*>(g_simb + (size_t)(bm + mloc) * NS + bn + ncl) =
                    pack_bf16x2(e0, e1);
            }
            #pragma unroll
            for (int o = 1; o < 4; o <<= 1) {
                lm = fmaxf(lm, __shfl_xor_sync(0xffffffffu, lm, o));
                ls += __shfl_xor_sync(0xffffffffu, ls, o);
            }
            if (t == 0) {
                s_max[wn*128 + mloc] = lm;
                s_sum[wn*128 + mloc] = ls;
            }
        }
    __syncthreads();
    if (tid < 128) {
        float m = s_max[tid]; float s = s_sum[tid];
        #pragma unroll
        for (int wq = 1; wq < 4; wq++) {
            m = fmaxf(m, s_max[wq*128 + tid]);
            s += s_sum[wq*128 + tid];
        }
        size_t pidx = (size_t)(bm + tid) * NBLK + blockIdx.x;
        g_pmax[pidx] = m; g_psum[pidx] = s;
    }
}

// ------- combine: Z + two-stage argmax (block -> slot via E) + wcomb + topk --
__global__ void __launch_bounds__(256) k_combine(const float* __restrict__ mem,
                                                 float* __restrict__ out2) {
    int b = blockIdx.x, t = threadIdx.x, lane = t & 31, w = t >> 5;
    size_t base = (size_t)b * NBLK;
    float p1 = g_pmax[base + t], p2 = g_pmax[base + t + 256];
    float m = fmaxf(p1, p2);
    float s = g_psum[base + t] + g_psum[base + t + 256];
    __shared__ float sm[256]; __shared__ float ss[256];
    __shared__ float s_q[DD];
    __shared__ int s_cnt, s_cand[64];
    __shared__ int s_scnt, s_slot[64];
    __shared__ float s_bv[8]; __shared__ int s_bi[8];
    __shared__ int s_arg;
    if (t == 0) { s_cnt = 0; s_scnt = 0; }
    if (t < 64) reinterpret_cast<float4*>(s_q)[t] =
        reinterpret_cast<const float4*>(g_qn + (size_t)b * DD)[t];
    sm[t] = m; ss[t] = s; __syncthreads();
    for (int o = 128; o; o >>= 1) {
        if (t < o) { ss[t] += ss[t+o]; sm[t] = fmaxf(sm[t], sm[t+o]); }
        __syncthreads();
    }
    float rm = sm[0];
    if (t == 0) {
        g_cZinv[b] = 1.0f / ss[0];
        float s1 = 0.f, s2 = 0.f;
        #pragma unroll
        for (int c = 0; c < WCH; c++) { s1 += g_ws1[b*WCH + c]; s2 += g_ws2[b*WCH + c]; }
        float sinv = 1.0f / (s1 + 1e-8f);
        float z = (float)NS + s1 * sinv + 0.5f * s2 * sinv * sinv;
        g_wsinv[b] = sinv;
        g_wZinv[b] = 1.0f / z;
    }
    float thr = rm - 8e-3f;
    if (p1 >= thr) { int p = atomicAdd(&s_cnt, 1); if (p < 64) s_cand[p] = t; }
    if (p2 >= thr) { int p = atomicAdd(&s_cnt, 1); if (p < 64) s_cand[p] = t + 256; }
    __syncthreads();
    int nc = min(s_cnt, 64);
    float Eth = __expf(rm - 8e-3f) * 0.992f;
    const __nv_bfloat16* Erow = g_simb + (size_t)b * NS;
    for (int i = t; i < nc * 128; i += 256) {
        int n = s_cand[i >> 7] * 128 + (i & 127);
        if (__bfloat162float(Erow[n]) >= Eth) {
            int p = atomicAdd(&s_scnt, 1);
            if (p < 64) s_slot[p] = n;
        }
    }
    __syncthreads();
    int nsl = min(s_scnt, 64);
    float bv = -1e30f; int bi = 0x7fffffff;
    for (int c = w; c < nsl; c += 8) {
        int n = s_slot[c];
        const float* mr = mem + (size_t)n * DD;
        float d = 0.f;
        #pragma unroll
        for (int j = 0; j < 8; j += 4) {
            float4 qv = *reinterpret_cast<const float4*>(s_q + lane*8 + j);
            float4 mv = *reinterpret_cast<const float4*>(mr + lane*8 + j);
            d += qv.x*mv.x + qv.y*mv.y + qv.z*mv.z + qv.w*mv.w;
        }
        #pragma unroll
        for (int o = 16; o; o >>= 1) d += __shfl_xor_sync(0xffffffffu, d, o);
        d *= g_minv[n];
        if (lane == 0) {
            if (d > bv || (d == bv && n < bi)) { bv = d; bi = n; }
        }
    }
    if (lane == 0) { s_bv[w] = bv; s_bi[w] = bi; }
    __syncthreads();
    if (t == 0) {
        float v = s_bv[0]; int ix = s_bi[0];
        #pragma unroll
        for (int k = 1; k < 8; k++)
            if (s_bv[k] > v || (s_bv[k] == v && s_bi[k] < ix)) { v = s_bv[k]; ix = s_bi[k]; }
        g_argmax[b] = ix;
        s_arg = ix;
    }
    __syncthreads();
    out2[(size_t)b * DD + t] = mem[(size_t)s_arg * DD + t];
}

// ======= merged GEMM kernel, 256 threads, 128x128 tiles, 2 CTA/SM ===========
// content blocks 0..255 (cp.async 6-stage): z=bx>>3, bm=((bx>>1)&3)*128, bd=(bx&1)*128
// newmem blocks 256..1279: bm=(bx>>1)*128, bd=(bx&1)*128
// content smem: A 6 @ s*10240 (61440), B 6 @ 61440+s*8704 (52224) => 113664
// newmem smem:  A 2 @ s*8704, B(async) 4 @ 17408+s*8704, red@52224,
//               sinv@60416, zinv@62464, erase@64512
#define CNM_DSM 113664
#define CONT_BLKS (SPLITS * 8)   // 256

__device__ __forceinline__ void content_body(int bx) {
    int tid = threadIdx.x, lane = tid & 31, w = tid >> 5;
    int wm = w >> 2, wn = w & 3;
    int z = bx >> 3, bm = ((bx >> 1) & 3) * 128, bd = (bx & 1) * 128;
    uint32_t sb = smem_u32(dsm);
    float acc[4][4][4];
    #pragma unroll
    for (int i = 0; i < 4; i++)
        #pragma unroll
        for (int j = 0; j < 4; j++)
            #pragma unroll
            for (int u = 0; u < 4; u++) acc[i][j][u] = 0.f;
    int r = lane & 7, gq = lane >> 3;
    int kbase = z * KCHUNK;
    const int NIT = KCHUNK / 32;   // 64

    auto issue = [&](int it, int st) {
        if (it < NIT) {
            int k0 = kbase + it * 32;
            uint32_t sa = sb + st * 10240;
            uint32_t sbb = sb + 61440 + st * 8704;
            #pragma unroll
            for (int i = 0; i < 2; i++) {
                int idx = tid + i * 256;
                int ar = idx >> 2, aq8 = (idx & 3) * 8;
                cp16(sa + (uint32_t)(ar*80 + aq8*2),
                     g_simb + (size_t)(bm + ar) * NS + k0 + aq8);
                int br = idx >> 4, bq8 = (idx & 15) * 8;
                cp16(sbb + (uint32_t)(br*272 + bq8*2),
                     g_memb + (size_t)(k0 + br) * DD + bd + bq8);
            }
        }
        CP_COMMIT();
    };
    issue(0, 0); issue(1, 1); issue(2, 2); issue(3, 3); issue(4, 4);

    int st = 0, pst = 5;
    for (int it = 0; it < NIT; it++) {
        CP_WAIT4();
        __syncthreads();
        issue(it + 5, pst);
        if (++pst == 6) pst = 0;
        uint32_t aA = sb + st * 10240;
        uint32_t aB = sb + 61440 + st * 8704;
        if (++st == 6) st = 0;
        #pragma unroll
        for (int ks = 0; ks < 2; ks++) {
            int kk = ks * 16;
            uint32_t af[4][4], bf[2][4];
            #pragma unroll
            for (int mt = 0; mt < 4; mt++) {
                int arow = wm*64 + mt*16 + r + 8*(gq & 1);
                int acol = kk + 8*(gq >> 1);
                ldsm4(af[mt], aA + (uint32_t)(arow*80 + acol*2));
            }
            #pragma unroll
            for (int np = 0; np < 2; np++) {
                int brow = kk + r + 8*(gq & 1);
                int bcol = wn*32 + np*16 + 8*(gq >> 1);
                ldsm4t(bf[np], aB + (uint32_t)(brow*272 + bcol*2));
            }
            #pragma unroll
            for (int mt = 0; mt < 4; mt++)
                #pragma unroll
                for (int nt = 0; nt < 4; nt++) {
                    int np = nt >> 1, hb = (nt & 1) * 2;
                    mma_bf16(acc[mt][nt], af[mt], bf[np][hb], bf[np][hb+1]);
                }
        }
    }
    int g = lane >> 2, tq = lane & 3;
    #pragma unroll
    for (int mt = 0; mt < 4; mt++)
        #pragma unroll
        for (int rs = 0; rs < 2; rs++) {
            int mloc = wm*64 + mt*16 + g + rs*8;
            float* dst = g_partial + ((size_t)z * NB + bm + mloc) * DD + bd;
            #pragma unroll
            for (int nt = 0; nt < 4; nt++) {
                int off = wn*32 + nt*8 + tq*2;
                *reinterpret_cast<float2*>(dst + off) =
                    make_float2(acc[mt][nt][rs*2], acc[mt][nt][rs*2+1]);
            }
        }
}

__device__ __forceinline__ void newmem_body(int bx, const float* __restrict__ mem,
                                            float* __restrict__ out3) {
    char* pA[2] = { dsm, dsm + 8704 };            // 32 x 128 bf16 (w), stride 272
    uint32_t sbB = smem_u32(dsm) + 17408;         // B (valb): 4 async stages of 8704
    float* s_red   = reinterpret_cast<float*>(dsm + 52224);   // [16][128]
    float* s_sinv  = reinterpret_cast<float*>(dsm + 60416);
    float* s_zinv  = reinterpret_cast<float*>(dsm + 62464);
    float* s_erase = reinterpret_cast<float*>(dsm + 64512);
    int tid = threadIdx.x, lane = tid & 31, w = tid >> 5;
    int wm = w >> 2, wn = w & 3;
    int bm = (bx >> 1) * 128, bd = (bx & 1) * 128;
    if (tid < 128) {
        reinterpret_cast<float4*>(s_sinv)[tid] = reinterpret_cast<const float4*>(g_wsinv)[tid];
        reinterpret_cast<float4*>(s_zinv)[tid] = reinterpret_cast<const float4*>(g_wZinv)[tid];
    }
    float acc[4][4][4];
    #pragma unroll
    for (int i = 0; i < 4; i++)
        #pragma unroll
        for (int j = 0; j < 4; j++)
            #pragma unroll
            for (int u = 0; u < 4; u++) acc[i][j][u] = 0.f;
    float pr[8];
    #pragma unroll
    for (int j = 0; j < 8; j++) pr[j] = 1.f;
    int r = lane & 7, gq = lane >> 3;
    int ac8 = (tid & 15) * 8;

    auto issueB = [&](int it) {
        if (it < 16) {
            int k0 = it * 32;
            uint32_t sbb = sbB + (it & 3) * 8704;
            #pragma unroll
            for (int i = 0; i < 2; i++) {
                int idx = tid + i * 256;
                int br = idx >> 4, bq8 = (idx & 15) * 8;
                cp16(sbb + (uint32_t)(br*272 + bq8*2),
                     g_valb + (size_t)(k0 + br) * DD + bd + bq8);
            }
        }
        CP_COMMIT();
    };
    issueB(0); issueB(1); issueB(2);
    __syncthreads();   // s_sinv/zinv visible before storeA

    auto storeA = [&](int st, int rowoff, int krow, uint4 u) {
        float sv = s_sinv[krow], zv = s_zinv[krow];
        float f[8];
        unpack2(u.x, f[0], f[1]); unpack2(u.y, f[2], f[3]);
        unpack2(u.z, f[4], f[5]); unpack2(u.w, f[6], f[7]);
        uint32_t stv[4];
        #pragma unroll
        for (int j = 0; j < 8; j += 2) {
            float x0 = f[j] * sv, x1 = f[j+1] * sv;
            float w0 = (1.f + x0 + 0.5f*x0*x0) * zv;
            float w1 = (1.f + x1 + 0.5f*x1*x1) * zv;
            pr[j]   *= (1.f - 0.5f*w0);
            pr[j+1] *= (1.f - 0.5f*w1);
            stv[j >> 1] = pack_bf16x2(w0, w1);
        }
        *reinterpret_cast<uint4*>(pA[st] + rowoff*272 + ac8*2) =
            make_uint4(stv[0], stv[1], stv[2], stv[3]);
    };

    {   // A chunk 0
        #pragma unroll
        for (int i = 0; i < 2; i++) {
            int idx = tid + i * 256;
            int ar = idx >> 4;
            uint4 u = *reinterpret_cast<const uint4*>(g_wwb + (size_t)ar * NS + bm + ac8);
            storeA(0, ar, ar, u);
        }
    }
    __syncthreads();

    uint4 pfa[2];
    for (int ch = 0; ch < 16; ch++) {
        int st = ch & 1;
        if (ch < 15) {
            int k0 = (ch + 1) * 32;
            #pragma unroll
            for (int i = 0; i < 2; i++) {
                int idx = tid + i * 256;
                int ar = idx >> 4;
                pfa[i] = *reinterpret_cast<const uint4*>(g_wwb + (size_t)(k0 + ar) * NS + bm + ac8);
            }
        }
        CP_WAIT2();
        __syncthreads();
        issueB(ch + 3);
        uint32_t aA = smem_u32(pA[st]);
        uint32_t aB = sbB + (ch & 3) * 8704;
        #pragma unroll
        for (int ks = 0; ks < 2; ks++) {
            int kk = ks * 16;
            uint32_t af[4][4], bf[2][4];
            #pragma unroll
            for (int mt = 0; mt < 4; mt++) {
                int arow = kk + r + 8*(gq >> 1);
                int acol = wm*64 + mt*16 + 8*(gq & 1);
                ldsm4t(af[mt], aA + (uint32_t)(arow*272 + acol*2));
            }
            #pragma unroll
            for (int np = 0; np < 2; np++) {
                int brow = kk + r + 8*(gq & 1);
                int bcol = wn*32 + np*16 + 8*(gq >> 1);
                ldsm4t(bf[np], aB + (uint32_t)(brow*272 + bcol*2));
            }
            #pragma unroll
            for (int mt = 0; mt < 4; mt++)
                #pragma unroll
                for (int nt = 0; nt < 4; nt++) {
                    int np = nt >> 1, hb = (nt & 1) * 2;
                    mma_bf16(acc[mt][nt], af[mt], bf[np][hb], bf[np][hb+1]);
                }
        }
        if (ch < 15) {
            int ns = st ^ 1;
            int k0 = (ch + 1) * 32;
            #pragma unroll
            for (int i = 0; i < 2; i++) {
                int idx = tid + i * 256;
                int ar = idx >> 4;
                storeA(ns, ar, k0 + ar, pfa[i]);
            }
        }
    }
    __syncthreads();
    #pragma unroll
    for (int j = 0; j < 8; j++) s_red[(tid >> 4)*128 + ac8 + j] = pr[j];
    __syncthreads();
    if (tid < 128) {
        float p = 1.f;
        #pragma unroll
        for (int k = 0; k < 16; k++) p *= s_red[k*128 + tid];
        s_erase[tid] = p;
    }
    __syncthreads();
    int g = lane >> 2, tq = lane & 3;
    #pragma unroll
    for (int mt = 0; mt < 4; mt++)
        #pragma unroll
        for (int rs = 0; rs < 2; rs++) {
            int mloc = wm*64 + mt*16 + g + rs*8;
            int slot = bm + mloc;
            float er = s_erase[mloc];
            const float* mrow = mem + (size_t)slot * DD + bd;
            float* dst = out3 + (size_t)slot * DD + bd;
            #pragma unroll
            for (int nt = 0; nt < 4; nt++) {
                int off = wn*32 + nt*8 + tq*2;
                float2 mv = *reinterpret_cast<const float2*>(mrow + off);
                *reinterpret_cast<float2*>(dst + off) =
                    make_float2(mv.x*er + acc[mt][nt][rs*2], mv.y*er + acc[mt][nt][rs*2+1]);
            }
        }
}

__global__ void __launch_bounds__(256, 2) k_cnm(const float* __restrict__ mem,
                                                float* __restrict__ out3) {
    if (blockIdx.x < CONT_BLKS) content_body(blockIdx.x);
    else                        newmem_body(blockIdx.x - CONT_BLKS, mem, out3);
}

// ---------------- reduce split-K partials, scale by 1/Z ----------------------
__global__ void __launch_bounds__(256) k_reduce(float* __restrict__ out1) {
    int idx = blockIdx.x * 256 + threadIdx.x;
    int b = idx >> 8;
    float s = 0.f;
    #pragma unroll
    for (int z = 0; z < SPLITS; z++) s += g_partial[(size_t)z * NB * DD + idx];
    out1[idx] = s * g_cZinv[b];
}

// ---------------- launch ----------------------------------------------------
extern "C" void kernel_launch(void* const* d_in, const int* in_sizes, int n_in,
                              void* d_out, int out_size) {
    const float* memory  = (const float*)d_in[0];
    const float* query   = (const float*)d_in[1];
    const float* value   = (const float*)d_in[2];
    const float* prev    = (const float*)d_in[3];
    const float* shiftw  = (const float*)d_in[4];

    float* out  = (float*)d_out;
    float* out1 = out;                     // read_content [512,256]
    float* out2 = out + NB * DD;           // read_topk    [512,256]
    float* out3 = out + 2 * NB * DD;       // new_mem      [65536,256]

    cudaFuncSetAttribute(k_sim, cudaFuncAttributeMaxDynamicSharedMemorySize, SIM_DSM);
    cudaFuncSetAttribute(k_cnm, cudaFuncAttributeMaxDynamicSharedMemorySize, CNM_DSM);

    k_pre    <<<NB * WCH + (NS + 2*NB) / 8, 256>>>(memory, query, value, prev, shiftw);
    k_sim    <<<dim3(NS / 128, NB / 128), 256, SIM_DSM>>>();
    k_combine<<<NB, 256>>>(memory, out2);
    k_cnm    <<<CONT_BLKS + 2 * (NS / 128), 256, CNM_DSM>>>(memory, out3);
    k_reduce <<<(NB * DD) / 256, 256>>>(out1);
}

// round 16
// speedup vs baseline: 1.4169x; 1.2331x over previous
#include <cuda_runtime.h>
#include <cuda_bf16.h>
#include <math.h>
#include <stdint.h>

#define NB 512
#define NS 65536
#define DD 256
#define SPLITS 32
#define KCHUNK (NS / SPLITS)   // 2048
#define NBLK 512
#define WCH 8          // sharp chunks per row

// ---------------- scratch (device globals; no allocations allowed) ----------
__device__ __nv_bfloat16 g_simb[(size_t)NB * NS];   // 64 MB : E = exp(sim), bf16
__device__ __nv_bfloat16 g_memb[(size_t)NS * DD];   // 32 MB : bf16 memory
__device__ __nv_bfloat16 g_qnb [NB * DD];
__device__ float g_qn [NB * DD];
__device__ float g_minv[NS];
__device__ float g_pmax[(size_t)NB * NBLK];
__device__ float g_psum[(size_t)NB * NBLK];
__device__ int   g_argmax[NB];
__device__ float g_cZinv[NB];
__device__ float g_ws1[NB * WCH];
__device__ float g_ws2[NB * WCH];
__device__ float g_wZinv[NB];
__device__ float g_cvec[DD];
__device__ float g_erasec;
__device__ float g_partial[(size_t)SPLITS * NB * DD];  // 16 MB

// ======================= helpers ============================================
__device__ __forceinline__ uint32_t smem_u32(const void* p) {
    uint32_t a;
    asm("{ .reg .u64 t; cvta.to.shared.u64 t, %1; cvt.u32.u64 %0, t; }" : "=r"(a) : "l"(p));
    return a;
}
__device__ __forceinline__ uint32_t pack_bf16x2(float lo, float hi) {
    uint32_t r;
    asm("cvt.rn.bf16x2.f32 %0, %1, %2;" : "=r"(r) : "f"(hi), "f"(lo));
    return r;
}
__device__ __forceinline__ void unpack2(uint32_t u, float& a, float& b) {
    __nv_bfloat162 h = *reinterpret_cast<__nv_bfloat162*>(&u);
    a = __bfloat162float(h.x); b = __bfloat162float(h.y);
}
__device__ __forceinline__ void ldsm4(uint32_t* r, uint32_t addr) {
    asm volatile("ldmatrix.sync.aligned.m8n8.x4.shared.b16 {%0,%1,%2,%3}, [%4];"
        : "=r"(r[0]), "=r"(r[1]), "=r"(r[2]), "=r"(r[3]) : "r"(addr));
}
__device__ __forceinline__ void ldsm4t(uint32_t* r, uint32_t addr) {
    asm volatile("ldmatrix.sync.aligned.m8n8.x4.trans.shared.b16 {%0,%1,%2,%3}, [%4];"
        : "=r"(r[0]), "=r"(r[1]), "=r"(r[2]), "=r"(r[3]) : "r"(addr));
}
__device__ __forceinline__ void mma_bf16(float* c, const uint32_t* a, uint32_t b0, uint32_t b1) {
    asm volatile("mma.sync.aligned.m16n8k16.row.col.f32.bf16.bf16.f32 "
        "{%0,%1,%2,%3}, {%4,%5,%6,%7}, {%8,%9}, {%0,%1,%2,%3};"
        : "+f"(c[0]), "+f"(c[1]), "+f"(c[2]), "+f"(c[3])
        : "r"(a[0]), "r"(a[1]), "r"(a[2]), "r"(a[3]), "r"(b0), "r"(b1));
}
__device__ __forceinline__ void cp16(uint32_t d, const void* s) {
    asm volatile("cp.async.cg.shared.global [%0], [%1], 16;" :: "r"(d), "l"(s) : "memory");
}
#define CP_COMMIT() asm volatile("cp.async.commit_group;" ::: "memory")
#define CP_WAIT2()  asm volatile("cp.async.wait_group 2;" ::: "memory")
#define CP_WAIT4()  asm volatile("cp.async.wait_group 4;" ::: "memory")

extern __shared__ __align__(16) char dsm[];

// ===== merged pre-pass: sharp rowsums (blocks 0..4095) + norms/convert ======
__global__ void __launch_bounds__(256) k_pre(const float* __restrict__ mem,
                                             const float* __restrict__ q,
                                             const float* __restrict__ prev,
                                             const float* __restrict__ sw) {
    __shared__ float r1[256], r2[256];
    int bx = blockIdx.x, t = threadIdx.x;
    if (bx < NB * WCH) {
        // sharp: read-only rowsum pass (S1, S2) — no store needed
        int b = bx >> 3, ch = bx & 7, lane = t & 31;
        const float* row = prev + (size_t)b * NS;
        float w0 = sw[0], w1 = sw[1], w2 = sw[2];
        int base = ch * (NS / WCH);
        float s1 = 0.f, s2 = 0.f;
        #pragma unroll
        for (int it = 0; it < NS / WCH / 1024; it++) {
            int i4 = base + (it * 256 + t) * 4;
            float4 v = *reinterpret_cast<const float4*>(row + i4);
            float pl = __shfl_up_sync(0xffffffffu, v.w, 1);
            float nx = __shfl_down_sync(0xffffffffu, v.x, 1);
            if (lane == 0)  pl = (i4 > 0) ? row[i4 - 1] : 0.f;
            if (lane == 31) nx = (i4 + 4 < NS) ? row[i4 + 4] : 0.f;
            float a0 = pl*w0 + v.x*w1 + v.y*w2;
            float a1 = v.x*w0 + v.y*w1 + v.z*w2;
            float a2 = v.y*w0 + v.z*w1 + v.w*w2;
            float a3 = v.z*w0 + v.w*w1 + nx*w2;
            float p0 = a0*a0*rsqrtf(fmaxf(a0, 1e-35f));
            float p1 = a1*a1*rsqrtf(fmaxf(a1, 1e-35f));
            float p2 = a2*a2*rsqrtf(fmaxf(a2, 1e-35f));
            float p3 = a3*a3*rsqrtf(fmaxf(a3, 1e-35f));
            s1 += p0 + p1 + p2 + p3;
            s2 += p0*p0 + p1*p1 + p2*p2 + p3*p3;
        }
        r1[t] = s1; r2[t] = s2; __syncthreads();
        for (int o = 128; o; o >>= 1) {
            if (t < o) { r1[t] += r1[t+o]; r2[t] += r2[t+o]; }
            __syncthreads();
        }
        if (t == 0) { g_ws1[b * WCH + ch] = r1[0]; g_ws2[b * WCH + ch] = r2[0]; }
        return;
    }
    int lane = t & 31;
    int row = (bx - NB * WCH) * 8 + (t >> 5);
    if (row < NS) {
        const float4* p = reinterpret_cast<const float4*>(mem + (size_t)row * DD);
        float4 v0 = p[lane];
        float4 v1 = p[lane + 32];
        float s = v0.x*v0.x + v0.y*v0.y + v0.z*v0.z + v0.w*v0.w
                + v1.x*v1.x + v1.y*v1.y + v1.z*v1.z + v1.w*v1.w;
        #pragma unroll
        for (int o = 16; o; o >>= 1) s += __shfl_xor_sync(0xffffffffu, s, o);
        if (lane == 0) g_minv[row] = 1.0f / fmaxf(sqrtf(s), 1e-12f);
        __nv_bfloat16* d = g_memb + (size_t)row * DD;
        *reinterpret_cast<uint2*>(d + lane*4) =
            make_uint2(pack_bf16x2(v0.x, v0.y), pack_bf16x2(v0.z, v0.w));
        *reinterpret_cast<uint2*>(d + 128 + lane*4) =
            make_uint2(pack_bf16x2(v1.x, v1.y), pack_bf16x2(v1.z, v1.w));
    } else {
        int qr = row - NS;
        const float4* p = reinterpret_cast<const float4*>(q + (size_t)qr * DD);
        float4 v0 = p[lane];
        float4 v1 = p[lane + 32];
        float s = v0.x*v0.x + v0.y*v0.y + v0.z*v0.z + v0.w*v0.w
                + v1.x*v1.x + v1.y*v1.y + v1.z*v1.z + v1.w*v1.w;
        #pragma unroll
        for (int o = 16; o; o >>= 1) s += __shfl_xor_sync(0xffffffffu, s, o);
        float inv = 1.0f / fmaxf(sqrtf(s), 1e-12f);
        v0.x *= inv; v0.y *= inv; v0.z *= inv; v0.w *= inv;
        v1.x *= inv; v1.y *= inv; v1.z *= inv; v1.w *= inv;
        float4* o4 = reinterpret_cast<float4*>(g_qn + (size_t)qr * DD);
        o4[lane] = v0; o4[lane + 32] = v1;
        __nv_bfloat16* d = g_qnb + (size_t)qr * DD;
        *reinterpret_cast<uint2*>(d + lane*4) =
            make_uint2(pack_bf16x2(v0.x, v0.y), pack_bf16x2(v0.z, v0.w));
        *reinterpret_cast<uint2*>(d + 128 + lane*4) =
            make_uint2(pack_bf16x2(v1.x, v1.y), pack_bf16x2(v1.z, v1.w));
    }
}

// ------- write-softmax constants: Zinv per row, C0/C2, erase constant -------
__global__ void __launch_bounds__(512) k_wz() {
    __shared__ float c0[512], c2[512];
    int t = threadIdx.x;
    float s1 = 0.f, s2 = 0.f;
    #pragma unroll
    for (int c = 0; c < WCH; c++) { s1 += g_ws1[t*WCH + c]; s2 += g_ws2[t*WCH + c]; }
    float sinv = 1.0f / (s1 + 1e-8f);
    float z = (float)NS + s1 * sinv + 0.5f * s2 * sinv * sinv;
    float zi = 1.0f / z;
    g_wZinv[t] = zi;
    c0[t] = zi; c2[t] = zi * zi;
    __syncthreads();
    for (int o = 256; o; o >>= 1) {
        if (t < o) { c0[t] += c0[t+o]; c2[t] += c2[t+o]; }
        __syncthreads();
    }
    if (t == 0) g_erasec = __expf(-0.5f * c0[0] - 0.125f * c2[0]);
}

// ============ sim GEMM (HMMA bf16, cp.async 4-stage) + exp epilogue =========
// dsm: A stages s*10240 (4), B stages 40960+s*10240 (4), minv @ 81920
#define SIM_DSM 82432
__global__ void __launch_bounds__(256, 2) k_sim() {
    float* s_minv = reinterpret_cast<float*>(dsm + 81920);
    int tid = threadIdx.x, lane = tid & 31, w = tid >> 5;
    int wm = w >> 2, wn = w & 3;
    int bn = blockIdx.x * 128, bm = blockIdx.y * 128;
    uint32_t sb = smem_u32(dsm);
    if (tid < 32) reinterpret_cast<float4*>(s_minv)[tid] =
        reinterpret_cast<const float4*>(g_minv + bn)[tid];

    float acc[4][4][4];
    #pragma unroll
    for (int i = 0; i < 4; i++)
        #pragma unroll
        for (int j = 0; j < 4; j++)
            #pragma unroll
            for (int u = 0; u < 4; u++) acc[i][j][u] = 0.f;

    int r = lane & 7, gq = lane >> 3;

    auto issue = [&](int it) {
        if (it < 8) {
            int k0 = it * 32;
            uint32_t sa = sb + (it & 3) * 10240;
            uint32_t sbb = sb + 40960 + (it & 3) * 10240;
            #pragma unroll
            for (int i = 0; i < 2; i++) {
                int idx = tid + i * 256;
                int row = idx >> 2, q8 = (idx & 3) * 8;
                cp16(sa  + (uint32_t)(row*80 + q8*2), g_qnb  + (size_t)(bm + row) * DD + k0 + q8);
                cp16(sbb + (uint32_t)(row*80 + q8*2), g_memb + (size_t)(bn + row) * DD + k0 + q8);
            }
        }
        CP_COMMIT();
    };
    issue(0); issue(1); issue(2);

    for (int ch = 0; ch < 8; ch++) {
        CP_WAIT2();
        __syncthreads();
        issue(ch + 3);
        uint32_t aA = sb + (ch & 3) * 10240;
        uint32_t aB = sb + 40960 + (ch & 3) * 10240;
        #pragma unroll
        for (int ks = 0; ks < 2; ks++) {
            int kk = ks * 16;
            uint32_t ah[4][4], bh[2][4];
            #pragma unroll
            for (int mt = 0; mt < 4; mt++) {
                int arow = wm*64 + mt*16 + r + 8*(gq & 1);
                int acol = kk + 8*(gq >> 1);
                ldsm4(ah[mt], aA + (uint32_t)(arow*80 + acol*2));
            }
            #pragma unroll
            for (int np = 0; np < 2; np++) {
                int brow = wn*32 + np*16 + r + 8*(gq >> 1);
                int bcol = kk + 8*(gq & 1);
                ldsm4(bh[np], aB + (uint32_t)(brow*80 + bcol*2));
            }
            #pragma unroll
            for (int mt = 0; mt < 4; mt++)
                #pragma unroll
                for (int nt = 0; nt < 4; nt++) {
                    int np = nt >> 1, hb = (nt & 1) * 2;
                    mma_bf16(acc[mt][nt], ah[mt], bh[np][hb], bh[np][hb+1]);
                }
        }
    }
    __syncthreads();

    float* s_max = reinterpret_cast<float*>(dsm);
    float* s_sum = reinterpret_cast<float*>(dsm + 40960);
    int g = lane >> 2, t = lane & 3;
    #pragma unroll
    for (int mt = 0; mt < 4; mt++)
        #pragma unroll
        for (int rs = 0; rs < 2; rs++) {
            int mloc = wm*64 + mt*16 + g + rs*8;
            float lm = -1e30f; float ls = 0.f;
            #pragma unroll
            for (int nt = 0; nt < 4; nt++) {
                int ncl = wn*32 + nt*8 + t*2;
                float s0 = acc[mt][nt][rs*2]   * s_minv[ncl];
                float s1 = acc[mt][nt][rs*2+1] * s_minv[ncl+1];
                lm = fmaxf(lm, fmaxf(s0, s1));
                float e0 = __expf(s0), e1 = __expf(s1);
                ls += e0 + e1;
                *reinterpret_cast<uint32_t*>(g_simb + (size_t)(bm + mloc) * NS + bn + ncl) =
                    pack_bf16x2(e0, e1);
            }
            #pragma unroll
            for (int o = 1; o < 4; o <<= 1) {
                lm = fmaxf(lm, __shfl_xor_sync(0xffffffffu, lm, o));
                ls += __shfl_xor_sync(0xffffffffu, ls, o);
            }
            if (t == 0) {
                s_max[wn*128 + mloc] = lm;
                s_sum[wn*128 + mloc] = ls;
            }
        }
    __syncthreads();
    if (tid < 128) {
        float m = s_max[tid]; float s = s_sum[tid];
        #pragma unroll
        for (int wq = 1; wq < 4; wq++) {
            m = fmaxf(m, s_max[wq*128 + tid]);
            s += s_sum[wq*128 + tid];
        }
        size_t pidx = (size_t)(bm + tid) * NBLK + blockIdx.x;
        g_pmax[pidx] = m; g_psum[pidx] = s;
    }
}

// ------- combine: Z + two-stage argmax + topk (block NB: cvec) ---------------
__global__ void __launch_bounds__(256) k_combine(const float* __restrict__ mem,
                                                 const float* __restrict__ val,
                                                 float* __restrict__ out2) {
    int b = blockIdx.x, t = threadIdx.x, lane = t & 31, w = t >> 5;
    if (b == NB) {
        float a = 0.f;
        for (int bb = 0; bb < NB; bb++) a += val[(size_t)bb * DD + t] * g_wZinv[bb];
        g_cvec[t] = a;
        return;
    }
    size_t base = (size_t)b * NBLK;
    float p1 = g_pmax[base + t], p2 = g_pmax[base + t + 256];
    float m = fmaxf(p1, p2);
    float s = g_psum[base + t] + g_psum[base + t + 256];
    __shared__ float sm[256]; __shared__ float ss[256];
    __shared__ float s_q[DD];
    __shared__ int s_cnt, s_cand[64];
    __shared__ int s_scnt, s_slot[64];
    __shared__ float s_bv[8]; __shared__ int s_bi[8];
    __shared__ int s_arg;
    if (t == 0) { s_cnt = 0; s_scnt = 0; }
    if (t < 64) reinterpret_cast<float4*>(s_q)[t] =
        reinterpret_cast<const float4*>(g_qn + (size_t)b * DD)[t];
    sm[t] = m; ss[t] = s; __syncthreads();
    for (int o = 128; o; o >>= 1) {
        if (t < o) { ss[t] += ss[t+o]; sm[t] = fmaxf(sm[t], sm[t+o]); }
        __syncthreads();
    }
    float rm = sm[0];
    if (t == 0) g_cZinv[b] = 1.0f / ss[0];
    float thr = rm - 8e-3f;
    if (p1 >= thr) { int p = atomicAdd(&s_cnt, 1); if (p < 64) s_cand[p] = t; }
    if (p2 >= thr) { int p = atomicAdd(&s_cnt, 1); if (p < 64) s_cand[p] = t + 256; }
    __syncthreads();
    int nc = min(s_cnt, 64);
    float Eth = __expf(rm - 8e-3f) * 0.992f;
    const __nv_bfloat16* Erow = g_simb + (size_t)b * NS;
    for (int i = t; i < nc * 128; i += 256) {
        int n = s_cand[i >> 7] * 128 + (i & 127);
        if (__bfloat162float(Erow[n]) >= Eth) {
            int p = atomicAdd(&s_scnt, 1);
            if (p < 64) s_slot[p] = n;
        }
    }
    __syncthreads();
    int nsl = min(s_scnt, 64);
    float bv = -1e30f; int bi = 0x7fffffff;
    for (int c = w; c < nsl; c += 8) {
        int n = s_slot[c];
        const float* mr = mem + (size_t)n * DD;
        float d = 0.f;
        #pragma unroll
        for (int j = 0; j < 8; j += 4) {
            float4 qv = *reinterpret_cast<const float4*>(s_q + lane*8 + j);
            float4 mv = *reinterpret_cast<const float4*>(mr + lane*8 + j);
            d += qv.x*mv.x + qv.y*mv.y + qv.z*mv.z + qv.w*mv.w;
        }
        #pragma unroll
        for (int o = 16; o; o >>= 1) d += __shfl_xor_sync(0xffffffffu, d, o);
        d *= g_minv[n];
        if (lane == 0) {
            if (d > bv || (d == bv && n < bi)) { bv = d; bi = n; }
        }
    }
    if (lane == 0) { s_bv[w] = bv; s_bi[w] = bi; }
    __syncthreads();
    if (t == 0) {
        float v = s_bv[0]; int ix = s_bi[0];
        #pragma unroll
        for (int k = 1; k < 8; k++)
            if (s_bv[k] > v || (s_bv[k] == v && s_bi[k] < ix)) { v = s_bv[k]; ix = s_bi[k]; }
        g_argmax[b] = ix;
        s_arg = ix;
    }
    __syncthreads();
    out2[(size_t)b * DD + t] = mem[(size_t)s_arg * DD + t];
}

// ======= merged kernel: content GEMM (0..255) + newmem stream (256..767) ====
// content smem: A 6 @ s*10240 (61440), B 6 @ 61440+s*8704 (52224) => 113664
#define CNM_DSM 113664
#define CONT_BLKS (SPLITS * 8)   // 256

__device__ __forceinline__ void content_body(int bx) {
    int tid = threadIdx.x, lane = tid & 31, w = tid >> 5;
    int wm = w >> 2, wn = w & 3;
    int z = bx >> 3, bm = ((bx >> 1) & 3) * 128, bd = (bx & 1) * 128;
    uint32_t sb = smem_u32(dsm);
    float acc[4][4][4];
    #pragma unroll
    for (int i = 0; i < 4; i++)
        #pragma unroll
        for (int j = 0; j < 4; j++)
            #pragma unroll
            for (int u = 0; u < 4; u++) acc[i][j][u] = 0.f;
    int r = lane & 7, gq = lane >> 3;
    int kbase = z * KCHUNK;
    const int NIT = KCHUNK / 32;   // 64

    auto issue = [&](int it, int st) {
        if (it < NIT) {
            int k0 = kbase + it * 32;
            uint32_t sa = sb + st * 10240;
            uint32_t sbb = sb + 61440 + st * 8704;
            #pragma unroll
            for (int i = 0; i < 2; i++) {
                int idx = tid + i * 256;
                int ar = idx >> 2, aq8 = (idx & 3) * 8;
                cp16(sa + (uint32_t)(ar*80 + aq8*2),
                     g_simb + (size_t)(bm + ar) * NS + k0 + aq8);
                int br = idx >> 4, bq8 = (idx & 15) * 8;
                cp16(sbb + (uint32_t)(br*272 + bq8*2),
                     g_memb + (size_t)(k0 + br) * DD + bd + bq8);
            }
        }
        CP_COMMIT();
    };
    issue(0, 0); issue(1, 1); issue(2, 2); issue(3, 3); issue(4, 4);

    int st = 0, pst = 5;
    for (int it = 0; it < NIT; it++) {
        CP_WAIT4();
        __syncthreads();
        issue(it + 5, pst);
        if (++pst == 6) pst = 0;
        uint32_t aA = sb + st * 10240;
        uint32_t aB = sb + 61440 + st * 8704;
        if (++st == 6) st = 0;
        #pragma unroll
        for (int ks = 0; ks < 2; ks++) {
            int kk = ks * 16;
            uint32_t af[4][4], bf[2][4];
            #pragma unroll
            for (int mt = 0; mt < 4; mt++) {
                int arow = wm*64 + mt*16 + r + 8*(gq & 1);
                int acol = kk + 8*(gq >> 1);
                ldsm4(af[mt], aA + (uint32_t)(arow*80 + acol*2));
            }
            #pragma unroll
            for (int np = 0; np < 2; np++) {
                int brow = kk + r + 8*(gq & 1);
                int bcol = wn*32 + np*16 + 8*(gq >> 1);
                ldsm4t(bf[np], aB + (uint32_t)(brow*272 + bcol*2));
            }
            #pragma unroll
            for (int mt = 0; mt < 4; mt++)
                #pragma unroll
                for (int nt = 0; nt < 4; nt++) {
                    int np = nt >> 1, hb = (nt & 1) * 2;
                    mma_bf16(acc[mt][nt], af[mt], bf[np][hb], bf[np][hb+1]);
                }
        }
    }
    int g = lane >> 2, tq = lane & 3;
    #pragma unroll
    for (int mt = 0; mt < 4; mt++)
        #pragma unroll
        for (int rs = 0; rs < 2; rs++) {
            int mloc = wm*64 + mt*16 + g + rs*8;
            float* dst = g_partial + ((size_t)z * NB + bm + mloc) * DD + bd;
            #pragma unroll
            for (int nt = 0; nt < 4; nt++) {
                int off = wn*32 + nt*8 + tq*2;
                *reinterpret_cast<float2*>(dst + off) =
                    make_float2(acc[mt][nt][rs*2], acc[mt][nt][rs*2+1]);
            }
        }
}

// newmem stream: out3[n][d] = mem[n][d]*E_c + c[d]   (128 rows per block)
__device__ __forceinline__ void newmem_stream(int i, const float* __restrict__ mem,
                                              float* __restrict__ out3) {
    float* sc = reinterpret_cast<float*>(dsm);
    int tid = threadIdx.x;
    if (tid < 64) reinterpret_cast<float4*>(sc)[tid] =
        reinterpret_cast<const float4*>(g_cvec)[tid];
    __syncthreads();
    float ec = g_erasec;
    size_t base = (size_t)i * 128 * DD;
    const float4* src = reinterpret_cast<const float4*>(mem + base);
    float4* dst = reinterpret_cast<float4*>(out3 + base);
    #pragma unroll 4
    for (int j = tid; j < 128 * DD / 4; j += 256) {
        float4 v = src[j];
        int d = (j & 63) * 4;
        v.x = v.x * ec + sc[d];
        v.y = v.y * ec + sc[d + 1];
        v.z = v.z * ec + sc[d + 2];
        v.w = v.w * ec + sc[d + 3];
        dst[j] = v;
    }
}

__global__ void __launch_bounds__(256, 2) k_cnm(const float* __restrict__ mem,
                                                float* __restrict__ out3) {
    if (blockIdx.x < CONT_BLKS) content_body(blockIdx.x);
    else                        newmem_stream(blockIdx.x - CONT_BLKS, mem, out3);
}

// ---------------- reduce split-K partials, scale by 1/Z ----------------------
__global__ void __launch_bounds__(256) k_reduce(float* __restrict__ out1) {
    int idx = blockIdx.x * 256 + threadIdx.x;
    int b = idx >> 8;
    float s = 0.f;
    #pragma unroll
    for (int z = 0; z < SPLITS; z++) s += g_partial[(size_t)z * NB * DD + idx];
    out1[idx] = s * g_cZinv[b];
}

// ---------------- launch ----------------------------------------------------
extern "C" void kernel_launch(void* const* d_in, const int* in_sizes, int n_in,
                              void* d_out, int out_size) {
    const float* memory  = (const float*)d_in[0];
    const float* query   = (const float*)d_in[1];
    const float* value   = (const float*)d_in[2];
    const float* prev    = (const float*)d_in[3];
    const float* shiftw  = (const float*)d_in[4];

    float* out  = (float*)d_out;
    float* out1 = out;                     // read_content [512,256]
    float* out2 = out + NB * DD;           // read_topk    [512,256]
    float* out3 = out + 2 * NB * DD;       // new_mem      [65536,256]

    cudaFuncSetAttribute(k_sim, cudaFuncAttributeMaxDynamicSharedMemorySize, SIM_DSM);
    cudaFuncSetAttribute(k_cnm, cudaFuncAttributeMaxDynamicSharedMemorySize, CNM_DSM);

    k_pre    <<<NB * WCH + (NS + NB) / 8, 256>>>(memory, query, prev, shiftw);
    k_wz     <<<1, 512>>>();
    k_sim    <<<dim3(NS / 128, NB / 128), 256, SIM_DSM>>>();
    k_combine<<<NB + 1, 256>>>(memory, value, out2);
    k_cnm    <<<CONT_BLKS + NS / 128, 256, CNM_DSM>>>(memory, out3);
    k_reduce <<<(NB * DD) / 256, 256>>>(out1);
}

// round 17
// speedup vs baseline: 1.6267x; 1.1481x over previous
#include <cuda_runtime.h>
#include <cuda_bf16.h>
#include <math.h>
#include <stdint.h>

#define NB 512
#define NS 65536
#define DD 256
#define SPLITS 32
#define KCHUNK (NS / SPLITS)   // 2048
#define NBLK 512
#define WCH 8          // sharp chunks per row
#define CVP 16         // cvec partial blocks

// ---------------- scratch (device globals; no allocations allowed) ----------
__device__ __nv_bfloat16 g_simb[(size_t)NB * NS];   // 64 MB : E = exp(sim), bf16
__device__ __nv_bfloat16 g_memb[(size_t)NS * DD];   // 32 MB : bf16 memory
__device__ __nv_bfloat16 g_qnb [NB * DD];
__device__ float g_qn [NB * DD];
__device__ float g_minv[NS];
__device__ float g_pmax[(size_t)NB * NBLK];
__device__ float g_psum[(size_t)NB * NBLK];
__device__ int   g_argmax[NB];
__device__ float g_cZinv[NB];
__device__ float g_ws1[NB * WCH];
__device__ float g_ws2[NB * WCH];
__device__ float g_wZinv[NB];
__device__ float g_cvecp[CVP * DD];
__device__ float g_erasec;
__device__ float g_partial[(size_t)SPLITS * NB * DD];  // 16 MB

// ======================= helpers ============================================
__device__ __forceinline__ uint32_t smem_u32(const void* p) {
    uint32_t a;
    asm("{ .reg .u64 t; cvta.to.shared.u64 t, %1; cvt.u32.u64 %0, t; }" : "=r"(a) : "l"(p));
    return a;
}
__device__ __forceinline__ uint32_t pack_bf16x2(float lo, float hi) {
    uint32_t r;
    asm("cvt.rn.bf16x2.f32 %0, %1, %2;" : "=r"(r) : "f"(hi), "f"(lo));
    return r;
}
__device__ __forceinline__ void unpack2(uint32_t u, float& a, float& b) {
    __nv_bfloat162 h = *reinterpret_cast<__nv_bfloat162*>(&u);
    a = __bfloat162float(h.x); b = __bfloat162float(h.y);
}
__device__ __forceinline__ void ldsm4(uint32_t* r, uint32_t addr) {
    asm volatile("ldmatrix.sync.aligned.m8n8.x4.shared.b16 {%0,%1,%2,%3}, [%4];"
        : "=r"(r[0]), "=r"(r[1]), "=r"(r[2]), "=r"(r[3]) : "r"(addr));
}
__device__ __forceinline__ void ldsm4t(uint32_t* r, uint32_t addr) {
    asm volatile("ldmatrix.sync.aligned.m8n8.x4.trans.shared.b16 {%0,%1,%2,%3}, [%4];"
        : "=r"(r[0]), "=r"(r[1]), "=r"(r[2]), "=r"(r[3]) : "r"(addr));
}
__device__ __forceinline__ void mma_bf16(float* c, const uint32_t* a, uint32_t b0, uint32_t b1) {
    asm volatile("mma.sync.aligned.m16n8k16.row.col.f32.bf16.bf16.f32 "
        "{%0,%1,%2,%3}, {%4,%5,%6,%7}, {%8,%9}, {%0,%1,%2,%3};"
        : "+f"(c[0]), "+f"(c[1]), "+f"(c[2]), "+f"(c[3])
        : "r"(a[0]), "r"(a[1]), "r"(a[2]), "r"(a[3]), "r"(b0), "r"(b1));
}
__device__ __forceinline__ void cp16(uint32_t d, const void* s) {
    asm volatile("cp.async.cg.shared.global [%0], [%1], 16;" :: "r"(d), "l"(s) : "memory");
}
#define CP_COMMIT() asm volatile("cp.async.commit_group;" ::: "memory")
#define CP_WAIT2()  asm volatile("cp.async.wait_group 2;" ::: "memory")
#define CP_WAIT4()  asm volatile("cp.async.wait_group 4;" ::: "memory")

extern __shared__ __align__(16) char dsm[];

// ===== merged pre-pass: sharp rowsums (blocks 0..4095) + norms/convert ======
__global__ void __launch_bounds__(256) k_pre(const float* __restrict__ mem,
                                             const float* __restrict__ q,
                                             const float* __restrict__ prev,
                                             const float* __restrict__ sw) {
    __shared__ float r1[256], r2[256];
    int bx = blockIdx.x, t = threadIdx.x;
    if (bx < NB * WCH) {
        int b = bx >> 3, ch = bx & 7, lane = t & 31;
        const float* row = prev + (size_t)b * NS;
        float w0 = sw[0], w1 = sw[1], w2 = sw[2];
        int base = ch * (NS / WCH);
        float s1 = 0.f, s2 = 0.f;
        #pragma unroll
        for (int it = 0; it < NS / WCH / 1024; it++) {
            int i4 = base + (it * 256 + t) * 4;
            float4 v = *reinterpret_cast<const float4*>(row + i4);
            float pl = __shfl_up_sync(0xffffffffu, v.w, 1);
            float nx = __shfl_down_sync(0xffffffffu, v.x, 1);
            if (lane == 0)  pl = (i4 > 0) ? row[i4 - 1] : 0.f;
            if (lane == 31) nx = (i4 + 4 < NS) ? row[i4 + 4] : 0.f;
            float a0 = pl*w0 + v.x*w1 + v.y*w2;
            float a1 = v.x*w0 + v.y*w1 + v.z*w2;
            float a2 = v.y*w0 + v.z*w1 + v.w*w2;
            float a3 = v.z*w0 + v.w*w1 + nx*w2;
            float p0 = a0*a0*rsqrtf(fmaxf(a0, 1e-35f));
            float p1 = a1*a1*rsqrtf(fmaxf(a1, 1e-35f));
            float p2 = a2*a2*rsqrtf(fmaxf(a2, 1e-35f));
            float p3 = a3*a3*rsqrtf(fmaxf(a3, 1e-35f));
            s1 += p0 + p1 + p2 + p3;
            s2 += p0*p0 + p1*p1 + p2*p2 + p3*p3;
        }
        r1[t] = s1; r2[t] = s2; __syncthreads();
        for (int o = 128; o; o >>= 1) {
            if (t < o) { r1[t] += r1[t+o]; r2[t] += r2[t+o]; }
            __syncthreads();
        }
        if (t == 0) { g_ws1[b * WCH + ch] = r1[0]; g_ws2[b * WCH + ch] = r2[0]; }
        return;
    }
    int lane = t & 31;
    int row = (bx - NB * WCH) * 8 + (t >> 5);
    if (row < NS) {
        const float4* p = reinterpret_cast<const float4*>(mem + (size_t)row * DD);
        float4 v0 = p[lane];
        float4 v1 = p[lane + 32];
        float s = v0.x*v0.x + v0.y*v0.y + v0.z*v0.z + v0.w*v0.w
                + v1.x*v1.x + v1.y*v1.y + v1.z*v1.z + v1.w*v1.w;
        #pragma unroll
        for (int o = 16; o; o >>= 1) s += __shfl_xor_sync(0xffffffffu, s, o);
        if (lane == 0) g_minv[row] = 1.0f / fmaxf(sqrtf(s), 1e-12f);
        __nv_bfloat16* d = g_memb + (size_t)row * DD;
        *reinterpret_cast<uint2*>(d + lane*4) =
            make_uint2(pack_bf16x2(v0.x, v0.y), pack_bf16x2(v0.z, v0.w));
        *reinterpret_cast<uint2*>(d + 128 + lane*4) =
            make_uint2(pack_bf16x2(v1.x, v1.y), pack_bf16x2(v1.z, v1.w));
    } else {
        int qr = row - NS;
        const float4* p = reinterpret_cast<const float4*>(q + (size_t)qr * DD);
        float4 v0 = p[lane];
        float4 v1 = p[lane + 32];
        float s = v0.x*v0.x + v0.y*v0.y + v0.z*v0.z + v0.w*v0.w
                + v1.x*v1.x + v1.y*v1.y + v1.z*v1.z + v1.w*v1.w;
        #pragma unroll
        for (int o = 16; o; o >>= 1) s += __shfl_xor_sync(0xffffffffu, s, o);
        float inv = 1.0f / fmaxf(sqrtf(s), 1e-12f);
        v0.x *= inv; v0.y *= inv; v0.z *= inv; v0.w *= inv;
        v1.x *= inv; v1.y *= inv; v1.z *= inv; v1.w *= inv;
        float4* o4 = reinterpret_cast<float4*>(g_qn + (size_t)qr * DD);
        o4[lane] = v0; o4[lane + 32] = v1;
        __nv_bfloat16* d = g_qnb + (size_t)qr * DD;
        *reinterpret_cast<uint2*>(d + lane*4) =
            make_uint2(pack_bf16x2(v0.x, v0.y), pack_bf16x2(v0.z, v0.w));
        *reinterpret_cast<uint2*>(d + 128 + lane*4) =
            make_uint2(pack_bf16x2(v1.x, v1.y), pack_bf16x2(v1.z, v1.w));
    }
}

// ------- write-softmax constants: Zinv per row, C0/C2, erase constant -------
__global__ void __launch_bounds__(512) k_wz() {
    __shared__ float c0[512], c2[512];
    int t = threadIdx.x;
    float s1 = 0.f, s2 = 0.f;
    #pragma unroll
    for (int c = 0; c < WCH; c++) { s1 += g_ws1[t*WCH + c]; s2 += g_ws2[t*WCH + c]; }
    float sinv = 1.0f / (s1 + 1e-8f);
    float z = (float)NS + s1 * sinv + 0.5f * s2 * sinv * sinv;
    float zi = 1.0f / z;
    g_wZinv[t] = zi;
    c0[t] = zi; c2[t] = zi * zi;
    __syncthreads();
    for (int o = 256; o; o >>= 1) {
        if (t < o) { c0[t] += c0[t+o]; c2[t] += c2[t+o]; }
        __syncthreads();
    }
    if (t == 0) g_erasec = __expf(-0.5f * c0[0] - 0.125f * c2[0]);
}

// ============ sim GEMM (HMMA bf16, cp.async 4-stage) + exp epilogue =========
// dsm: A stages s*10240 (4), B stages 40960+s*10240 (4), minv @ 81920
#define SIM_DSM 82432
__global__ void __launch_bounds__(256, 2) k_sim() {
    float* s_minv = reinterpret_cast<float*>(dsm + 81920);
    int tid = threadIdx.x, lane = tid & 31, w = tid >> 5;
    int wm = w >> 2, wn = w & 3;
    int bn = blockIdx.x * 128, bm = blockIdx.y * 128;
    uint32_t sb = smem_u32(dsm);
    if (tid < 32) reinterpret_cast<float4*>(s_minv)[tid] =
        reinterpret_cast<const float4*>(g_minv + bn)[tid];

    float acc[4][4][4];
    #pragma unroll
    for (int i = 0; i < 4; i++)
        #pragma unroll
        for (int j = 0; j < 4; j++)
            #pragma unroll
            for (int u = 0; u < 4; u++) acc[i][j][u] = 0.f;

    int r = lane & 7, gq = lane >> 3;

    auto issue = [&](int it) {
        if (it < 8) {
            int k0 = it * 32;
            uint32_t sa = sb + (it & 3) * 10240;
            uint32_t sbb = sb + 40960 + (it & 3) * 10240;
            #pragma unroll
            for (int i = 0; i < 2; i++) {
                int idx = tid + i * 256;
                int row = idx >> 2, q8 = (idx & 3) * 8;
                cp16(sa  + (uint32_t)(row*80 + q8*2), g_qnb  + (size_t)(bm + row) * DD + k0 + q8);
                cp16(sbb + (uint32_t)(row*80 + q8*2), g_memb + (size_t)(bn + row) * DD + k0 + q8);
            }
        }
        CP_COMMIT();
    };
    issue(0); issue(1); issue(2);

    for (int ch = 0; ch < 8; ch++) {
        CP_WAIT2();
        __syncthreads();
        issue(ch + 3);
        uint32_t aA = sb + (ch & 3) * 10240;
        uint32_t aB = sb + 40960 + (ch & 3) * 10240;
        #pragma unroll
        for (int ks = 0; ks < 2; ks++) {
            int kk = ks * 16;
            uint32_t ah[4][4], bh[2][4];
            #pragma unroll
            for (int mt = 0; mt < 4; mt++) {
                int arow = wm*64 + mt*16 + r + 8*(gq & 1);
                int acol = kk + 8*(gq >> 1);
                ldsm4(ah[mt], aA + (uint32_t)(arow*80 + acol*2));
            }
            #pragma unroll
            for (int np = 0; np < 2; np++) {
                int brow = wn*32 + np*16 + r + 8*(gq >> 1);
                int bcol = kk + 8*(gq & 1);
                ldsm4(bh[np], aB + (uint32_t)(brow*80 + bcol*2));
            }
            #pragma unroll
            for (int mt = 0; mt < 4; mt++)
                #pragma unroll
                for (int nt = 0; nt < 4; nt++) {
                    int np = nt >> 1, hb = (nt & 1) * 2;
                    mma_bf16(acc[mt][nt], ah[mt], bh[np][hb], bh[np][hb+1]);
                }
        }
    }
    __syncthreads();

    float* s_max = reinterpret_cast<float*>(dsm);
    float* s_sum = reinterpret_cast<float*>(dsm + 40960);
    int g = lane >> 2, t = lane & 3;
    #pragma unroll
    for (int mt = 0; mt < 4; mt++)
        #pragma unroll
        for (int rs = 0; rs < 2; rs++) {
            int mloc = wm*64 + mt*16 + g + rs*8;
            float lm = -1e30f; float ls = 0.f;
            #pragma unroll
            for (int nt = 0; nt < 4; nt++) {
                int ncl = wn*32 + nt*8 + t*2;
                float s0 = acc[mt][nt][rs*2]   * s_minv[ncl];
                float s1 = acc[mt][nt][rs*2+1] * s_minv[ncl+1];
                lm = fmaxf(lm, fmaxf(s0, s1));
                float e0 = __expf(s0), e1 = __expf(s1);
                ls += e0 + e1;
                *reinterpret_cast<uint32_t*>(g_simb + (size_t)(bm + mloc) * NS + bn + ncl) =
                    pack_bf16x2(e0, e1);
            }
            #pragma unroll
            for (int o = 1; o < 4; o <<= 1) {
                lm = fmaxf(lm, __shfl_xor_sync(0xffffffffu, lm, o));
                ls += __shfl_xor_sync(0xffffffffu, ls, o);
            }
            if (t == 0) {
                s_max[wn*128 + mloc] = lm;
                s_sum[wn*128 + mloc] = ls;
            }
        }
    __syncthreads();
    if (tid < 128) {
        float m = s_max[tid]; float s = s_sum[tid];
        #pragma unroll
        for (int wq = 1; wq < 4; wq++) {
            m = fmaxf(m, s_max[wq*128 + tid]);
            s += s_sum[wq*128 + tid];
        }
        size_t pidx = (size_t)(bm + tid) * NBLK + blockIdx.x;
        g_pmax[pidx] = m; g_psum[pidx] = s;
    }
}

// ------- combine: Z + two-stage argmax + topk (blocks NB..NB+15: cvec) -------
__global__ void __launch_bounds__(256) k_combine(const float* __restrict__ mem,
                                                 const float* __restrict__ val,
                                                 float* __restrict__ out2) {
    int b = blockIdx.x, t = threadIdx.x, lane = t & 31, w = t >> 5;
    if (b >= NB) {
        // cvec partial p: sum over 32 batch rows (fixed order -> deterministic)
        int p = b - NB;
        float a = 0.f;
        #pragma unroll
        for (int j = 0; j < NB / CVP; j++) {
            int bb = p * (NB / CVP) + j;
            a += val[(size_t)bb * DD + t] * g_wZinv[bb];
        }
        g_cvecp[p * DD + t] = a;
        return;
    }
    size_t base = (size_t)b * NBLK;
    float p1 = g_pmax[base + t], p2 = g_pmax[base + t + 256];
    float m = fmaxf(p1, p2);
    float s = g_psum[base + t] + g_psum[base + t + 256];
    __shared__ float sm[256]; __shared__ float ss[256];
    __shared__ float s_q[DD];
    __shared__ int s_cnt, s_cand[64];
    __shared__ int s_scnt, s_slot[64];
    __shared__ float s_bv[8]; __shared__ int s_bi[8];
    __shared__ int s_arg;
    if (t == 0) { s_cnt = 0; s_scnt = 0; }
    if (t < 64) reinterpret_cast<float4*>(s_q)[t] =
        reinterpret_cast<const float4*>(g_qn + (size_t)b * DD)[t];
    sm[t] = m; ss[t] = s; __syncthreads();
    for (int o = 128; o; o >>= 1) {
        if (t < o) { ss[t] += ss[t+o]; sm[t] = fmaxf(sm[t], sm[t+o]); }
        __syncthreads();
    }
    float rm = sm[0];
    if (t == 0) g_cZinv[b] = 1.0f / ss[0];
    float thr = rm - 8e-3f;
    if (p1 >= thr) { int p = atomicAdd(&s_cnt, 1); if (p < 64) s_cand[p] = t; }
    if (p2 >= thr) { int p = atomicAdd(&s_cnt, 1); if (p < 64) s_cand[p] = t + 256; }
    __syncthreads();
    int nc = min(s_cnt, 64);
    float Eth = __expf(rm - 8e-3f) * 0.992f;
    const __nv_bfloat16* Erow = g_simb + (size_t)b * NS;
    for (int i = t; i < nc * 128; i += 256) {
        int n = s_cand[i >> 7] * 128 + (i & 127);
        if (__bfloat162float(Erow[n]) >= Eth) {
            int p = atomicAdd(&s_scnt, 1);
            if (p < 64) s_slot[p] = n;
        }
    }
    __syncthreads();
    int nsl = min(s_scnt, 64);
    float bv = -1e30f; int bi = 0x7fffffff;
    for (int c = w; c < nsl; c += 8) {
        int n = s_slot[c];
        const float* mr = mem + (size_t)n * DD;
        float d = 0.f;
        #pragma unroll
        for (int j = 0; j < 8; j += 4) {
            float4 qv = *reinterpret_cast<const float4*>(s_q + lane*8 + j);
            float4 mv = *reinterpret_cast<const float4*>(mr + lane*8 + j);
            d += qv.x*mv.x + qv.y*mv.y + qv.z*mv.z + qv.w*mv.w;
        }
        #pragma unroll
        for (int o = 16; o; o >>= 1) d += __shfl_xor_sync(0xffffffffu, d, o);
        d *= g_minv[n];
        if (lane == 0) {
            if (d > bv || (d == bv && n < bi)) { bv = d; bi = n; }
        }
    }
    if (lane == 0) { s_bv[w] = bv; s_bi[w] = bi; }
    __syncthreads();
    if (t == 0) {
        float v = s_bv[0]; int ix = s_bi[0];
        #pragma unroll
        for (int k = 1; k < 8; k++)
            if (s_bv[k] > v || (s_bv[k] == v && s_bi[k] < ix)) { v = s_bv[k]; ix = s_bi[k]; }
        g_argmax[b] = ix;
        s_arg = ix;
    }
    __syncthreads();
    out2[(size_t)b * DD + t] = mem[(size_t)s_arg * DD + t];
}

// ======= merged kernel: content GEMM (0..255) + newmem stream (256..767) ====
// content smem: A 6 @ s*10240 (61440), B 6 @ 61440+s*8704 (52224) => 113664
#define CNM_DSM 113664
#define CONT_BLKS (SPLITS * 8)   // 256

__device__ __forceinline__ void content_body(int bx) {
    int tid = threadIdx.x, lane = tid & 31, w = tid >> 5;
    int wm = w >> 2, wn = w & 3;
    int z = bx >> 3, bm = ((bx >> 1) & 3) * 128, bd = (bx & 1) * 128;
    uint32_t sb = smem_u32(dsm);
    float acc[4][4][4];
    #pragma unroll
    for (int i = 0; i < 4; i++)
        #pragma unroll
        for (int j = 0; j < 4; j++)
            #pragma unroll
            for (int u = 0; u < 4; u++) acc[i][j][u] = 0.f;
    int r = lane & 7, gq = lane >> 3;
    int kbase = z * KCHUNK;
    const int NIT = KCHUNK / 32;   // 64

    auto issue = [&](int it, int st) {
        if (it < NIT) {
            int k0 = kbase + it * 32;
            uint32_t sa = sb + st * 10240;
            uint32_t sbb = sb + 61440 + st * 8704;
            #pragma unroll
            for (int i = 0; i < 2; i++) {
                int idx = tid + i * 256;
                int ar = idx >> 2, aq8 = (idx & 3) * 8;
                cp16(sa + (uint32_t)(ar*80 + aq8*2),
                     g_simb + (size_t)(bm + ar) * NS + k0 + aq8);
                int br = idx >> 4, bq8 = (idx & 15) * 8;
                cp16(sbb + (uint32_t)(br*272 + bq8*2),
                     g_memb + (size_t)(k0 + br) * DD + bd + bq8);
            }
        }
        CP_COMMIT();
    };
    issue(0, 0); issue(1, 1); issue(2, 2); issue(3, 3); issue(4, 4);

    int st = 0, pst = 5;
    for (int it = 0; it < NIT; it++) {
        CP_WAIT4();
        __syncthreads();
        issue(it + 5, pst);
        if (++pst == 6) pst = 0;
        uint32_t aA = sb + st * 10240;
        uint32_t aB = sb + 61440 + st * 8704;
        if (++st == 6) st = 0;
        #pragma unroll
        for (int ks = 0; ks < 2; ks++) {
            int kk = ks * 16;
            uint32_t af[4][4], bf[2][4];
            #pragma unroll
            for (int mt = 0; mt < 4; mt++) {
                int arow = wm*64 + mt*16 + r + 8*(gq & 1);
                int acol = kk + 8*(gq >> 1);
                ldsm4(af[mt], aA + (uint32_t)(arow*80 + acol*2));
            }
            #pragma unroll
            for (int np = 0; np < 2; np++) {
                int brow = kk + r + 8*(gq & 1);
                int bcol = wn*32 + np*16 + 8*(gq >> 1);
                ldsm4t(bf[np], aB + (uint32_t)(brow*272 + bcol*2));
            }
            #pragma unroll
            for (int mt = 0; mt < 4; mt++)
                #pragma unroll
                for (int nt = 0; nt < 4; nt++) {
                    int np = nt >> 1, hb = (nt & 1) * 2;
                    mma_bf16(acc[mt][nt], af[mt], bf[np][hb], bf[np][hb+1]);
                }
        }
    }
    int g = lane >> 2, tq = lane & 3;
    #pragma unroll
    for (int mt = 0; mt < 4; mt++)
        #pragma unroll
        for (int rs = 0; rs < 2; rs++) {
            int mloc = wm*64 + mt*16 + g + rs*8;
            float* dst = g_partial + ((size_t)z * NB + bm + mloc) * DD + bd;
            #pragma unroll
            for (int nt = 0; nt < 4; nt++) {
                int off = wn*32 + nt*8 + tq*2;
                *reinterpret_cast<float2*>(dst + off) =
                    make_float2(acc[mt][nt][rs*2], acc[mt][nt][rs*2+1]);
            }
        }
}

// newmem stream: out3[n][d] = mem[n][d]*E_c + c[d]   (128 rows per block)
__device__ __forceinline__ void newmem_stream(int i, const float* __restrict__ mem,
                                              float* __restrict__ out3) {
    float* sc = reinterpret_cast<float*>(dsm);
    int tid = threadIdx.x;
    if (tid < DD) {
        float a = 0.f;
        #pragma unroll
        for (int p = 0; p < CVP; p++) a += g_cvecp[p * DD + tid];
        sc[tid] = a;
    }
    __syncthreads();
    float ec = g_erasec;
    size_t base = (size_t)i * 128 * DD;
    const float4* src = reinterpret_cast<const float4*>(mem + base);
    float4* dst = reinterpret_cast<float4*>(out3 + base);
    #pragma unroll 4
    for (int j = tid; j < 128 * DD / 4; j += 256) {
        float4 v = src[j];
        int d = (j & 63) * 4;
        v.x = v.x * ec + sc[d];
        v.y = v.y * ec + sc[d + 1];
        v.z = v.z * ec + sc[d + 2];
        v.w = v.w * ec + sc[d + 3];
        dst[j] = v;
    }
}

__global__ void __launch_bounds__(256, 2) k_cnm(const float* __restrict__ mem,
                                                float* __restrict__ out3) {
    if (blockIdx.x < CONT_BLKS) content_body(blockIdx.x);
    else                        newmem_stream(blockIdx.x - CONT_BLKS, mem, out3);
}

// ---------------- reduce split-K partials, scale by 1/Z ----------------------
__global__ void __launch_bounds__(256) k_reduce(float* __restrict__ out1) {
    int idx = blockIdx.x * 256 + threadIdx.x;
    int b = idx >> 8;
    float s = 0.f;
    #pragma unroll
    for (int z = 0; z < SPLITS; z++) s += g_partial[(size_t)z * NB * DD + idx];
    out1[idx] = s * g_cZinv[b];
}

// ---------------- launch ----------------------------------------------------
extern "C" void kernel_launch(void* const* d_in, const int* in_sizes, int n_in,
                              void* d_out, int out_size) {
    const float* memory  = (const float*)d_in[0];
    const float* query   = (const float*)d_in[1];
    const float* value   = (const float*)d_in[2];
    const float* prev    = (const float*)d_in[3];
    const float* shiftw  = (const float*)d_in[4];

    float* out  = (float*)d_out;
    float* out1 = out;                     // read_content [512,256]
    float* out2 = out + NB * DD;           // read_topk    [512,256]
    float* out3 = out + 2 * NB * DD;       // new_mem      [65536,256]

    cudaFuncSetAttribute(k_sim, cudaFuncAttributeMaxDynamicSharedMemorySize, SIM_DSM);
    cudaFuncSetAttribute(k_cnm, cudaFuncAttributeMaxDynamicSharedMemorySize, CNM_DSM);

    k_pre    <<<NB * WCH + (NS + NB) / 8, 256>>>(memory, query, prev, shiftw);
    k_wz     <<<1, 512>>>();
    k_sim    <<<dim3(NS / 128, NB / 128), 256, SIM_DSM>>>();
    k_combine<<<NB + CVP, 256>>>(memory, value, out2);
    k_cnm    <<<CONT_BLKS + NS / 128, 256, CNM_DSM>>>(memory, out3);
    k_reduce <<<(NB * DD) / 256, 256>>>(out1);
}